// round 6
// baseline (speedup 1.0000x reference)
#include <cuda_runtime.h>
#include <math.h>

// ---------------------------------------------------------------------------
// localAE: two stacked GCNConv layers.
//   loc_emb = GCN(x, W_enc, b_enc)          [N, 64]
//   loc_rec = GCN(loc_emb, W_dec, b_dec)    [N, 128]
// GCN(x) = D^-1/2 (A+I) D^-1/2 (x W) + b, deg = in-degree(dst) + 1
//
// Pipeline (linearity of aggregation used for the decoder):
//   g_h = x @ W_enc                          (gemm 128->64, W in smem)
//   emb = dinv[d]*(sum h[s]*dinv[s] + h[d]*dinv[d]) + b_enc  (CSR gather)
//   g_h = dinv[d]*(sum emb[s]*dinv[s] + emb[d]*dinv[d])      (CSR gather)
//   rec = g_h @ W_dec + b_dec                (gemm 64->128, W in smem)
// CSR built per launch (grouped by dst) -> no feature atomics.
// ---------------------------------------------------------------------------

#define NN   100000
#define EMAX 1600000
#define NB_SCAN ((NN + 1023) / 1024)   // 98

// scratch (static device globals: allocation-free)
__device__ float g_h[(size_t)NN * 64];
__device__ float g_dinv[NN];
__device__ int   g_cnt[NN];             // in-degree (without self loop)
__device__ int   g_ptr[NN];             // CSR row start
__device__ int   g_cur[NN];             // fill cursor
__device__ int   g_csr[EMAX];           // src ids grouped by dst
__device__ int   g_bsum[NB_SCAN];
__device__ int   g_boff[NB_SCAN];

// ---------------------------------------------------------------------------
__global__ void k_zero_cnt(int n) {
    int i = blockIdx.x * blockDim.x + threadIdx.x;
    if (i < n) g_cnt[i] = 0;
}

__global__ void k_hist(const int* __restrict__ dst, int E) {
    int e = blockIdx.x * blockDim.x + threadIdx.x;
    if (e < E) atomicAdd(&g_cnt[dst[e]], 1);
}

// ---- scan stage 1 (shuffle-based) + dinv fused -----------------------------
__global__ void k_scan1(int n) {           // block = 1024
    int t = threadIdx.x;
    int lane = t & 31, wid = t >> 5;
    int gi = blockIdx.x * 1024 + t;
    int v = (gi < n) ? g_cnt[gi] : 0;
    if (gi < n) g_dinv[gi] = 1.0f / sqrtf((float)(v + 1));  // +1 self loop

    int x = v;
#pragma unroll
    for (int o = 1; o < 32; o <<= 1) {
        int y = __shfl_up_sync(0xffffffffu, x, o);
        if (lane >= o) x += y;
    }
    __shared__ int wsum[32];
    if (lane == 31) wsum[wid] = x;
    __syncthreads();
    if (wid == 0) {
        int s = wsum[lane];
#pragma unroll
        for (int o = 1; o < 32; o <<= 1) {
            int y = __shfl_up_sync(0xffffffffu, s, o);
            if (lane >= o) s += y;
        }
        wsum[lane] = s;
    }
    __syncthreads();
    int base = (wid > 0) ? wsum[wid - 1] : 0;
    int incl = x + base;
    if (gi < n) g_ptr[gi] = incl - v;        // exclusive
    if (t == 1023) g_bsum[blockIdx.x] = incl;
}

__global__ void k_scan2(int nb) {           // single block, 128 threads
    __shared__ int sh[128];
    int t = threadIdx.x;
    int v = (t < nb) ? g_bsum[t] : 0;
    sh[t] = v;
    __syncthreads();
#pragma unroll
    for (int off = 1; off < 128; off <<= 1) {
        int a = (t >= off) ? sh[t - off] : 0;
        __syncthreads();
        sh[t] += a;
        __syncthreads();
    }
    if (t < nb) g_boff[t] = sh[t] - v;       // exclusive
}

__global__ void k_scan3(int n) {            // block = 1024
    int gi = blockIdx.x * 1024 + threadIdx.x;
    if (gi < n) {
        int p = g_ptr[gi] + g_boff[blockIdx.x];
        g_ptr[gi] = p;
        g_cur[gi] = p;
    }
}

__global__ void k_fill(const int* __restrict__ src, const int* __restrict__ dst,
                       int E) {
    int e = blockIdx.x * blockDim.x + threadIdx.x;
    if (e < E) {
        int pos = atomicAdd(&g_cur[dst[e]], 1);
        g_csr[pos] = src[e];
    }
}

// ---------------------------------------------------------------------------
// CSR aggregation at 64 channels. One warp per node.
// ---------------------------------------------------------------------------
template<bool BIAS>
__global__ void k_agg64(const float* __restrict__ feat,
                        float* __restrict__ out,
                        const float* __restrict__ B, int n) {
    int w    = (blockIdx.x * blockDim.x + threadIdx.x) >> 5;   // node
    int lane = threadIdx.x & 31;
    if (w >= n) return;
    int c4   = lane & 15;        // float4 channel group
    int half = lane >> 4;        // 0 or 1
    int start = g_ptr[w];
    int cnt   = g_cnt[w];

    float4 acc = make_float4(0.f, 0.f, 0.f, 0.f);
    for (int k = half; k < cnt; k += 2) {
        int s = g_csr[start + k];
        float sc = g_dinv[s];
        float4 v = *(const float4*)(feat + (size_t)s * 64 + c4 * 4);
        acc.x += v.x * sc; acc.y += v.y * sc;
        acc.z += v.z * sc; acc.w += v.w * sc;
    }
    if (half == 0) {             // self loop
        float sc = g_dinv[w];
        float4 v = *(const float4*)(feat + (size_t)w * 64 + c4 * 4);
        acc.x += v.x * sc; acc.y += v.y * sc;
        acc.z += v.z * sc; acc.w += v.w * sc;
    }
    acc.x += __shfl_down_sync(0xffffffffu, acc.x, 16);
    acc.y += __shfl_down_sync(0xffffffffu, acc.y, 16);
    acc.z += __shfl_down_sync(0xffffffffu, acc.z, 16);
    acc.w += __shfl_down_sync(0xffffffffu, acc.w, 16);

    if (half == 0) {
        float dd = g_dinv[w];
        float4 o;
        if (BIAS) {
            float4 bv = *(const float4*)(B + c4 * 4);
            o = make_float4(acc.x * dd + bv.x, acc.y * dd + bv.y,
                            acc.z * dd + bv.z, acc.w * dd + bv.w);
        } else {
            o = make_float4(acc.x * dd, acc.y * dd, acc.z * dd, acc.w * dd);
        }
        *(float4*)(out + (size_t)w * 64 + c4 * 4) = o;
    }
}

// ---------------------------------------------------------------------------
// GEMM: OUT[n, COUT] = X[n, CIN] @ W[CIN, COUT] (+bias)
// Whole W resident in smem (32 KB); X streamed directly from global
// (channel-group threads of one node share a (half-)warp -> broadcast loads).
// No mainloop syncthreads. Thread tile: 8 nodes x 4 channels.
// ---------------------------------------------------------------------------
template<int CIN, int COUT, bool BIAS>
__global__ void __launch_bounds__(256)
k_gemm(const float* __restrict__ X, const float* __restrict__ W,
       const float* __restrict__ B, float* __restrict__ OUT, int n) {
    constexpr int TM = 8, TN = 4;
    constexpr int NT = 256;
    constexpr int CG = COUT / TN;        // 16 (enc) / 32 (dec)
    constexpr int NG = NT / CG;          // 16 / 8
    constexpr int BM = NG * TM;          // 128 / 64
    __shared__ float ws[CIN * COUT];     // 32 KB both layers

    const int t = threadIdx.x;
#pragma unroll
    for (int i = t * 4; i < CIN * COUT; i += NT * 4)
        *(float4*)(ws + i) = *(const float4*)(W + i);
    __syncthreads();

    const int cg = t % CG;
    const int ng = t / CG;
    const int n0 = blockIdx.x * BM + ng * TM;

    // clamped row pointers (tail blocks read node n-1; stores are guarded)
    const float* xp[TM];
#pragma unroll
    for (int i = 0; i < TM; i++) {
        int node = n0 + i;
        if (node > n - 1) node = n - 1;
        xp[i] = X + (size_t)node * CIN;
    }

    float4 acc[TM];
#pragma unroll
    for (int i = 0; i < TM; i++) acc[i] = make_float4(0.f, 0.f, 0.f, 0.f);

#pragma unroll 2
    for (int k = 0; k < CIN; k += 4) {
        float4 w0 = *(const float4*)(ws + (k + 0) * COUT + cg * 4);
        float4 w1 = *(const float4*)(ws + (k + 1) * COUT + cg * 4);
        float4 w2 = *(const float4*)(ws + (k + 2) * COUT + cg * 4);
        float4 w3 = *(const float4*)(ws + (k + 3) * COUT + cg * 4);
#pragma unroll
        for (int i = 0; i < TM; i++) {
            float4 xv = *(const float4*)(xp[i] + k);
            acc[i].x += xv.x * w0.x + xv.y * w1.x + xv.z * w2.x + xv.w * w3.x;
            acc[i].y += xv.x * w0.y + xv.y * w1.y + xv.z * w2.y + xv.w * w3.y;
            acc[i].z += xv.x * w0.z + xv.y * w1.z + xv.z * w2.z + xv.w * w3.z;
            acc[i].w += xv.x * w0.w + xv.y * w1.w + xv.z * w2.w + xv.w * w3.w;
        }
    }

    float4 bv = make_float4(0.f, 0.f, 0.f, 0.f);
    if (BIAS) bv = *(const float4*)(B + cg * 4);
#pragma unroll
    for (int i = 0; i < TM; i++) {
        int node = n0 + i;
        if (node < n) {
            float4 o = acc[i];
            if (BIAS) { o.x += bv.x; o.y += bv.y; o.z += bv.z; o.w += bv.w; }
            *(float4*)(OUT + (size_t)node * COUT + cg * 4) = o;
        }
    }
}

// ---------------------------------------------------------------------------
extern "C" void kernel_launch(void* const* d_in, const int* in_sizes, int n_in,
                              void* d_out, int out_size) {
    const float* x     = (const float*)d_in[0];
    const int*   ei    = (const int*)d_in[1];
    const float* W_enc = (const float*)d_in[2];
    const float* b_enc = (const float*)d_in[3];
    const float* W_dec = (const float*)d_in[4];
    const float* b_dec = (const float*)d_in[5];

    const int N = in_sizes[0] / 128;   // 100000
    const int E = in_sizes[1] / 2;     // 1600000
    const int* src = ei;
    const int* dst = ei + E;

    float* out_emb = (float*)d_out;                 // [N, 64]
    float* out_rec = out_emb + (size_t)N * 64;      // [N, 128]

    // real device address of the scratch symbol (host shadow addr is invalid)
    float* hbuf = nullptr;
    cudaGetSymbolAddress((void**)&hbuf, g_h);

    const int TB = 256;
    const int nbN = (N + TB - 1) / TB;
    const int nbE = (E + TB - 1) / TB;

    // ---- degree + dinv + CSR build ----
    k_zero_cnt<<<nbN, TB>>>(N);
    k_hist<<<nbE, TB>>>(dst, E);
    k_scan1<<<NB_SCAN, 1024>>>(N);           // also writes g_dinv
    k_scan2<<<1, 128>>>(NB_SCAN);
    k_scan3<<<NB_SCAN, 1024>>>(N);
    k_fill<<<nbE, TB>>>(src, dst, E);

    // ---- layer 1 (encoder): gemm (128->64) then CSR aggregate + bias ----
    k_gemm<128, 64, false><<<(N + 127) / 128, 256>>>(x, W_enc, nullptr, hbuf, N);
    {
        int blocks = (N * 32 + TB - 1) / TB;   // warp per node
        k_agg64<true><<<blocks, TB>>>(hbuf, out_emb, b_enc, N);
    }

    // ---- layer 2 (decoder): CSR aggregate (no bias) then gemm (64->128) ----
    {
        int blocks = (N * 32 + TB - 1) / TB;
        k_agg64<false><<<blocks, TB>>>(out_emb, hbuf, N ? nullptr : nullptr, N);
    }
    k_gemm<64, 128, true><<<(N + 63) / 64, 256>>>(hbuf, W_dec, b_dec, out_rec, N);
}

// round 7
// speedup vs baseline: 1.0877x; 1.0877x over previous
#include <cuda_runtime.h>
#include <math.h>

// ---------------------------------------------------------------------------
// localAE: two stacked GCNConv layers.
//   loc_emb = GCN(x, W_enc, b_enc)          [N, 64]
//   loc_rec = GCN(loc_emb, W_dec, b_dec)    [N, 128]
// GCN(x) = D^-1/2 (A+I) D^-1/2 (x W) + b, deg = in-degree(dst) + 1
//
// Pipeline (linearity of aggregation used for the decoder):
//   g_h = x @ W_enc                          (gemm 128->64)
//   emb = dinv[d]*(sum h[s]*dinv[s] + h[d]*dinv[d]) + b_enc  (CSR gather)
//   g_h = dinv[d]*(sum emb[s]*dinv[s] + emb[d]*dinv[d])      (CSR gather)
//   rec = g_h @ W_dec + b_dec                (gemm 64->128)
// GEMM: W and X block-tile both fully resident in dynamic smem, ONE barrier,
// sync-free FFMA mainloop, interleaved node rows for bank-conflict-free LDS.
// ---------------------------------------------------------------------------

#define NN   100000
#define EMAX 1600000
#define NB_SCAN ((NN + 1023) / 1024)   // 98

// scratch (static device globals: allocation-free)
__device__ float g_h[(size_t)NN * 64];
__device__ float g_dinv[NN];
__device__ int   g_cnt[NN];             // in-degree (without self loop)
__device__ int   g_ptr[NN];             // CSR row start
__device__ int   g_cur[NN];             // fill cursor
__device__ int   g_csr[EMAX];           // src ids grouped by dst
__device__ int   g_bsum[NB_SCAN];
__device__ int   g_boff[NB_SCAN];

// ---------------------------------------------------------------------------
__global__ void k_hist(const int* __restrict__ dst, int E) {
    int e = blockIdx.x * blockDim.x + threadIdx.x;
    if (e < E) atomicAdd(&g_cnt[dst[e]], 1);
}

// ---- scan stage 1 (shuffle-based) + dinv fused -----------------------------
__global__ void k_scan1(int n) {           // block = 1024
    int t = threadIdx.x;
    int lane = t & 31, wid = t >> 5;
    int gi = blockIdx.x * 1024 + t;
    int v = (gi < n) ? g_cnt[gi] : 0;
    if (gi < n) g_dinv[gi] = 1.0f / sqrtf((float)(v + 1));  // +1 self loop

    int x = v;
#pragma unroll
    for (int o = 1; o < 32; o <<= 1) {
        int y = __shfl_up_sync(0xffffffffu, x, o);
        if (lane >= o) x += y;
    }
    __shared__ int wsum[32];
    if (lane == 31) wsum[wid] = x;
    __syncthreads();
    if (wid == 0) {
        int s = wsum[lane];
#pragma unroll
        for (int o = 1; o < 32; o <<= 1) {
            int y = __shfl_up_sync(0xffffffffu, s, o);
            if (lane >= o) s += y;
        }
        wsum[lane] = s;
    }
    __syncthreads();
    int base = (wid > 0) ? wsum[wid - 1] : 0;
    int incl = x + base;
    if (gi < n) g_ptr[gi] = incl - v;        // exclusive
    if (t == 1023) g_bsum[blockIdx.x] = incl;
}

__global__ void k_scan2(int nb) {           // single block, 128 threads
    __shared__ int sh[128];
    int t = threadIdx.x;
    int v = (t < nb) ? g_bsum[t] : 0;
    sh[t] = v;
    __syncthreads();
#pragma unroll
    for (int off = 1; off < 128; off <<= 1) {
        int a = (t >= off) ? sh[t - off] : 0;
        __syncthreads();
        sh[t] += a;
        __syncthreads();
    }
    if (t < nb) g_boff[t] = sh[t] - v;       // exclusive
}

__global__ void k_scan3(int n) {            // block = 1024
    int gi = blockIdx.x * 1024 + threadIdx.x;
    if (gi < n) {
        int p = g_ptr[gi] + g_boff[blockIdx.x];
        g_ptr[gi] = p;
        g_cur[gi] = p;
    }
}

__global__ void k_fill(const int* __restrict__ src, const int* __restrict__ dst,
                       int E) {
    int e = blockIdx.x * blockDim.x + threadIdx.x;
    if (e < E) {
        int pos = atomicAdd(&g_cur[dst[e]], 1);
        g_csr[pos] = src[e];
    }
}

// ---------------------------------------------------------------------------
// CSR aggregation at 64 channels. One warp per node.
// ---------------------------------------------------------------------------
template<bool BIAS>
__global__ void k_agg64(const float* __restrict__ feat,
                        float* __restrict__ out,
                        const float* __restrict__ B, int n) {
    int w    = (blockIdx.x * blockDim.x + threadIdx.x) >> 5;   // node
    int lane = threadIdx.x & 31;
    if (w >= n) return;
    int c4   = lane & 15;        // float4 channel group
    int half = lane >> 4;        // 0 or 1
    int start = g_ptr[w];
    int cnt   = g_cnt[w];

    float4 acc = make_float4(0.f, 0.f, 0.f, 0.f);
    for (int k = half; k < cnt; k += 2) {
        int s = g_csr[start + k];
        float sc = g_dinv[s];
        float4 v = *(const float4*)(feat + (size_t)s * 64 + c4 * 4);
        acc.x += v.x * sc; acc.y += v.y * sc;
        acc.z += v.z * sc; acc.w += v.w * sc;
    }
    if (half == 0) {             // self loop
        float sc = g_dinv[w];
        float4 v = *(const float4*)(feat + (size_t)w * 64 + c4 * 4);
        acc.x += v.x * sc; acc.y += v.y * sc;
        acc.z += v.z * sc; acc.w += v.w * sc;
    }
    acc.x += __shfl_down_sync(0xffffffffu, acc.x, 16);
    acc.y += __shfl_down_sync(0xffffffffu, acc.y, 16);
    acc.z += __shfl_down_sync(0xffffffffu, acc.z, 16);
    acc.w += __shfl_down_sync(0xffffffffu, acc.w, 16);

    if (half == 0) {
        float dd = g_dinv[w];
        float4 o;
        if (BIAS) {
            float4 bv = *(const float4*)(B + c4 * 4);
            o = make_float4(acc.x * dd + bv.x, acc.y * dd + bv.y,
                            acc.z * dd + bv.z, acc.w * dd + bv.w);
        } else {
            o = make_float4(acc.x * dd, acc.y * dd, acc.z * dd, acc.w * dd);
        }
        *(float4*)(out + (size_t)w * 64 + c4 * 4) = o;
    }
}

// ---------------------------------------------------------------------------
// GEMM: OUT[n, COUT] = X[n, CIN] @ W[CIN, COUT] (+bias)
// Whole W (CIN*COUT) and whole X block-tile staged into dynamic smem once;
// single __syncthreads; sync-free mainloop.
// Node rows interleaved (row = i*NG + ng) -> the two half-warps touch adjacent
// xs rows (XP % 32 == 4 word offset) -> conflict-free LDS.128.
// Thread tile: 8 nodes x 4 channels.
// ---------------------------------------------------------------------------
template<int CIN, int COUT, bool BIAS>
__global__ void __launch_bounds__(256)
k_gemm(const float* __restrict__ X, const float* __restrict__ W,
       const float* __restrict__ B, float* __restrict__ OUT, int n) {
    constexpr int TM = 8, TN = 4;
    constexpr int NT = 256;
    constexpr int CG = COUT / TN;        // 16 (enc) / 32 (dec)
    constexpr int NG = NT / CG;          // 16 / 8
    constexpr int BM = NG * TM;          // 128 / 64
    constexpr int XP = CIN + 4;          // 132 / 68  (both ≡ 4 mod 32 words)
    extern __shared__ float sm[];
    float* ws = sm;                      // CIN*COUT
    float* xs = sm + CIN * COUT;         // BM*XP

    const int t  = threadIdx.x;
    const int n0 = blockIdx.x * BM;

    // stage W (once)
#pragma unroll
    for (int i = t * 4; i < CIN * COUT; i += NT * 4)
        *(float4*)(ws + i) = *(const float4*)(W + i);

    // stage X block tile (once); tail rows clamped to n-1, stores guarded
    for (int i = t * 4; i < BM * CIN; i += NT * 4) {
        int r = i / CIN, col = i % CIN;
        int node = n0 + r;
        if (node > n - 1) node = n - 1;
        *(float4*)(xs + r * XP + col) =
            *(const float4*)(X + (size_t)node * CIN + col);
    }
    __syncthreads();

    const int cg = t % CG;
    const int ng = t / CG;

    float4 acc[TM];
#pragma unroll
    for (int i = 0; i < TM; i++) acc[i] = make_float4(0.f, 0.f, 0.f, 0.f);

#pragma unroll 2
    for (int k = 0; k < CIN; k += 4) {
        float4 w0 = *(const float4*)(ws + (k + 0) * COUT + cg * 4);
        float4 w1 = *(const float4*)(ws + (k + 1) * COUT + cg * 4);
        float4 w2 = *(const float4*)(ws + (k + 2) * COUT + cg * 4);
        float4 w3 = *(const float4*)(ws + (k + 3) * COUT + cg * 4);
#pragma unroll
        for (int i = 0; i < TM; i++) {
            float4 xv = *(const float4*)(xs + (i * NG + ng) * XP + k);
            acc[i].x += xv.x * w0.x + xv.y * w1.x + xv.z * w2.x + xv.w * w3.x;
            acc[i].y += xv.x * w0.y + xv.y * w1.y + xv.z * w2.y + xv.w * w3.y;
            acc[i].z += xv.x * w0.z + xv.y * w1.z + xv.z * w2.z + xv.w * w3.z;
            acc[i].w += xv.x * w0.w + xv.y * w1.w + xv.z * w2.w + xv.w * w3.w;
        }
    }

    float4 bv = make_float4(0.f, 0.f, 0.f, 0.f);
    if (BIAS) bv = *(const float4*)(B + cg * 4);
#pragma unroll
    for (int i = 0; i < TM; i++) {
        int node = n0 + i * NG + ng;
        if (node < n) {
            float4 o = acc[i];
            if (BIAS) { o.x += bv.x; o.y += bv.y; o.z += bv.z; o.w += bv.w; }
            *(float4*)(OUT + (size_t)node * COUT + cg * 4) = o;
        }
    }
}

// ---------------------------------------------------------------------------
extern "C" void kernel_launch(void* const* d_in, const int* in_sizes, int n_in,
                              void* d_out, int out_size) {
    const float* x     = (const float*)d_in[0];
    const int*   ei    = (const int*)d_in[1];
    const float* W_enc = (const float*)d_in[2];
    const float* b_enc = (const float*)d_in[3];
    const float* W_dec = (const float*)d_in[4];
    const float* b_dec = (const float*)d_in[5];

    const int N = in_sizes[0] / 128;   // 100000
    const int E = in_sizes[1] / 2;     // 1600000
    const int* src = ei;
    const int* dst = ei + E;

    float* out_emb = (float*)d_out;                 // [N, 64]
    float* out_rec = out_emb + (size_t)N * 64;      // [N, 128]

    // real device addresses of scratch symbols (host shadow addr is invalid)
    float* hbuf = nullptr;
    cudaGetSymbolAddress((void**)&hbuf, g_h);
    int* cnt_dev = nullptr;
    cudaGetSymbolAddress((void**)&cnt_dev, g_cnt);

    // dynamic smem sizes (both > 48KB default cap)
    constexpr int SMEM_ENC = (128 * 64 + 128 * (128 + 4)) * 4;  // 100352
    constexpr int SMEM_DEC = (64 * 128 + 64 * (64 + 4)) * 4;    //  50176
    cudaFuncSetAttribute(k_gemm<128, 64, false>,
                         cudaFuncAttributeMaxDynamicSharedMemorySize, SMEM_ENC);
    cudaFuncSetAttribute(k_gemm<64, 128, true>,
                         cudaFuncAttributeMaxDynamicSharedMemorySize, SMEM_DEC);

    const int TB = 256;
    const int nbE = (E + TB - 1) / TB;

    // ---- degree + dinv + CSR build ----
    cudaMemsetAsync(cnt_dev, 0, (size_t)N * sizeof(int));
    k_hist<<<nbE, TB>>>(dst, E);
    k_scan1<<<NB_SCAN, 1024>>>(N);           // also writes g_dinv
    k_scan2<<<1, 128>>>(NB_SCAN);
    k_scan3<<<NB_SCAN, 1024>>>(N);
    k_fill<<<nbE, TB>>>(src, dst, E);

    // ---- layer 1 (encoder): gemm (128->64) then CSR aggregate + bias ----
    k_gemm<128, 64, false><<<(N + 127) / 128, 256, SMEM_ENC>>>(x, W_enc, nullptr, hbuf, N);
    {
        int blocks = (N * 32 + TB - 1) / TB;   // warp per node
        k_agg64<true><<<blocks, TB>>>(hbuf, out_emb, b_enc, N);
    }

    // ---- layer 2 (decoder): CSR aggregate (no bias) then gemm (64->128) ----
    {
        int blocks = (N * 32 + TB - 1) / TB;
        k_agg64<false><<<blocks, TB>>>(out_emb, hbuf, nullptr, N);
    }
    k_gemm<64, 128, true><<<(N + 63) / 64, 256, SMEM_DEC>>>(hbuf, W_dec, b_dec, out_rec, N);
}

// round 8
// speedup vs baseline: 1.1407x; 1.0487x over previous
#include <cuda_runtime.h>
#include <math.h>

// ---------------------------------------------------------------------------
// localAE: two stacked GCNConv layers.
//   loc_emb = GCN(x, W_enc, b_enc)          [N, 64]
//   loc_rec = GCN(loc_emb, W_dec, b_dec)    [N, 128]
// GCN(x) = D^-1/2 (A+I) D^-1/2 (x W) + b, deg = in-degree(dst) + 1
//
// Pipeline (linearity of aggregation used for the decoder):
//   g_h = x @ W_enc                          (gemm 128->64)   ── stream 0
//   CSR build (hist/scan/fill)               (independent)    ── side stream
//   emb = dinv[d]*(sum h[s]*dinv[s] + h[d]*dinv[d]) + b_enc   (CSR gather)
//   g_h = dinv[d]*(sum emb[s]*dinv[s] + emb[d]*dinv[d])       (CSR gather)
//   rec = g_h @ W_dec + b_dec                (gemm 64->128)
// GEMM: W and X block-tile fully resident in smem, ONE barrier, sync-free
// FFMA mainloop, interleaved node rows (conflict-free LDS.128).
// ---------------------------------------------------------------------------

#define NN   100000
#define EMAX 1600000
#define NB_SCAN ((NN + 1023) / 1024)   // 98

// scratch (static device globals: allocation-free)
__device__ float g_h[(size_t)NN * 64];
__device__ float g_dinv[NN];
__device__ int   g_cnt[NN];             // in-degree (without self loop)
__device__ int   g_ptr[NN];             // CSR row start
__device__ int   g_cur[NN];             // fill cursor
__device__ int   g_csr[EMAX];           // src ids grouped by dst
__device__ int   g_bsum[NB_SCAN];
__device__ int   g_boff[NB_SCAN];

// ---------------------------------------------------------------------------
__global__ void k_hist(const int* __restrict__ dst, int E) {
    int e = blockIdx.x * blockDim.x + threadIdx.x;
    if (e < E) atomicAdd(&g_cnt[dst[e]], 1);
}

// ---- scan stage 1 (shuffle-based) + dinv fused -----------------------------
__global__ void k_scan1(int n) {           // block = 1024
    int t = threadIdx.x;
    int lane = t & 31, wid = t >> 5;
    int gi = blockIdx.x * 1024 + t;
    int v = (gi < n) ? g_cnt[gi] : 0;
    if (gi < n) g_dinv[gi] = 1.0f / sqrtf((float)(v + 1));  // +1 self loop

    int x = v;
#pragma unroll
    for (int o = 1; o < 32; o <<= 1) {
        int y = __shfl_up_sync(0xffffffffu, x, o);
        if (lane >= o) x += y;
    }
    __shared__ int wsum[32];
    if (lane == 31) wsum[wid] = x;
    __syncthreads();
    if (wid == 0) {
        int s = wsum[lane];
#pragma unroll
        for (int o = 1; o < 32; o <<= 1) {
            int y = __shfl_up_sync(0xffffffffu, s, o);
            if (lane >= o) s += y;
        }
        wsum[lane] = s;
    }
    __syncthreads();
    int base = (wid > 0) ? wsum[wid - 1] : 0;
    int incl = x + base;
    if (gi < n) g_ptr[gi] = incl - v;        // exclusive
    if (t == 1023) g_bsum[blockIdx.x] = incl;
}

__global__ void k_scan2(int nb) {           // single block, 128 threads
    __shared__ int sh[128];
    int t = threadIdx.x;
    int v = (t < nb) ? g_bsum[t] : 0;
    sh[t] = v;
    __syncthreads();
#pragma unroll
    for (int off = 1; off < 128; off <<= 1) {
        int a = (t >= off) ? sh[t - off] : 0;
        __syncthreads();
        sh[t] += a;
        __syncthreads();
    }
    if (t < nb) g_boff[t] = sh[t] - v;       // exclusive
}

__global__ void k_scan3(int n) {            // block = 1024
    int gi = blockIdx.x * 1024 + threadIdx.x;
    if (gi < n) {
        int p = g_ptr[gi] + g_boff[blockIdx.x];
        g_ptr[gi] = p;
        g_cur[gi] = p;
    }
}

__global__ void k_fill(const int* __restrict__ src, const int* __restrict__ dst,
                       int E) {
    int e = blockIdx.x * blockDim.x + threadIdx.x;
    if (e < E) {
        int pos = atomicAdd(&g_cur[dst[e]], 1);
        g_csr[pos] = src[e];
    }
}

// ---------------------------------------------------------------------------
// CSR aggregation at 64 channels. One warp per node.
// ---------------------------------------------------------------------------
template<bool BIAS>
__global__ void k_agg64(const float* __restrict__ feat,
                        float* __restrict__ out,
                        const float* __restrict__ B, int n) {
    int w    = (blockIdx.x * blockDim.x + threadIdx.x) >> 5;   // node
    int lane = threadIdx.x & 31;
    if (w >= n) return;
    int c4   = lane & 15;        // float4 channel group
    int half = lane >> 4;        // 0 or 1
    int start = g_ptr[w];
    int cnt   = g_cnt[w];

    float4 acc = make_float4(0.f, 0.f, 0.f, 0.f);
    for (int k = half; k < cnt; k += 2) {
        int s = g_csr[start + k];
        float sc = g_dinv[s];
        float4 v = *(const float4*)(feat + (size_t)s * 64 + c4 * 4);
        acc.x += v.x * sc; acc.y += v.y * sc;
        acc.z += v.z * sc; acc.w += v.w * sc;
    }
    if (half == 0) {             // self loop
        float sc = g_dinv[w];
        float4 v = *(const float4*)(feat + (size_t)w * 64 + c4 * 4);
        acc.x += v.x * sc; acc.y += v.y * sc;
        acc.z += v.z * sc; acc.w += v.w * sc;
    }
    acc.x += __shfl_down_sync(0xffffffffu, acc.x, 16);
    acc.y += __shfl_down_sync(0xffffffffu, acc.y, 16);
    acc.z += __shfl_down_sync(0xffffffffu, acc.z, 16);
    acc.w += __shfl_down_sync(0xffffffffu, acc.w, 16);

    if (half == 0) {
        float dd = g_dinv[w];
        float4 o;
        if (BIAS) {
            float4 bv = *(const float4*)(B + c4 * 4);
            o = make_float4(acc.x * dd + bv.x, acc.y * dd + bv.y,
                            acc.z * dd + bv.z, acc.w * dd + bv.w);
        } else {
            o = make_float4(acc.x * dd, acc.y * dd, acc.z * dd, acc.w * dd);
        }
        *(float4*)(out + (size_t)w * 64 + c4 * 4) = o;
    }
}

// ---------------------------------------------------------------------------
// GEMM: OUT[n, COUT] = X[n, CIN] @ W[CIN, COUT] (+bias)
// Whole W and whole X block-tile staged into dynamic smem once; single
// __syncthreads; sync-free mainloop; interleaved node rows (conflict-free).
// Thread tile: 8 nodes x 4 channels.
// ---------------------------------------------------------------------------
template<int CIN, int COUT, bool BIAS>
__global__ void __launch_bounds__(256)
k_gemm(const float* __restrict__ X, const float* __restrict__ W,
       const float* __restrict__ B, float* __restrict__ OUT, int n) {
    constexpr int TM = 8, TN = 4;
    constexpr int NT = 256;
    constexpr int CG = COUT / TN;        // 16 (enc) / 32 (dec)
    constexpr int NG = NT / CG;          // 16 / 8
    constexpr int BM = NG * TM;          // 128 / 64
    constexpr int XP = CIN + 4;          // 132 / 68  (both ≡ 4 mod 32 words)
    extern __shared__ float sm[];
    float* ws = sm;                      // CIN*COUT
    float* xs = sm + CIN * COUT;         // BM*XP

    const int t  = threadIdx.x;
    const int n0 = blockIdx.x * BM;

    // stage W (once)
#pragma unroll
    for (int i = t * 4; i < CIN * COUT; i += NT * 4)
        *(float4*)(ws + i) = *(const float4*)(W + i);

    // stage X block tile (once); tail rows clamped to n-1, stores guarded
    for (int i = t * 4; i < BM * CIN; i += NT * 4) {
        int r = i / CIN, col = i % CIN;
        int node = n0 + r;
        if (node > n - 1) node = n - 1;
        *(float4*)(xs + r * XP + col) =
            *(const float4*)(X + (size_t)node * CIN + col);
    }
    __syncthreads();

    const int cg = t % CG;
    const int ng = t / CG;

    float4 acc[TM];
#pragma unroll
    for (int i = 0; i < TM; i++) acc[i] = make_float4(0.f, 0.f, 0.f, 0.f);

#pragma unroll 2
    for (int k = 0; k < CIN; k += 4) {
        float4 w0 = *(const float4*)(ws + (k + 0) * COUT + cg * 4);
        float4 w1 = *(const float4*)(ws + (k + 1) * COUT + cg * 4);
        float4 w2 = *(const float4*)(ws + (k + 2) * COUT + cg * 4);
        float4 w3 = *(const float4*)(ws + (k + 3) * COUT + cg * 4);
#pragma unroll
        for (int i = 0; i < TM; i++) {
            float4 xv = *(const float4*)(xs + (i * NG + ng) * XP + k);
            acc[i].x += xv.x * w0.x + xv.y * w1.x + xv.z * w2.x + xv.w * w3.x;
            acc[i].y += xv.x * w0.y + xv.y * w1.y + xv.z * w2.y + xv.w * w3.y;
            acc[i].z += xv.x * w0.z + xv.y * w1.z + xv.z * w2.z + xv.w * w3.z;
            acc[i].w += xv.x * w0.w + xv.y * w1.w + xv.z * w2.w + xv.w * w3.w;
        }
    }

    float4 bv = make_float4(0.f, 0.f, 0.f, 0.f);
    if (BIAS) bv = *(const float4*)(B + cg * 4);
#pragma unroll
    for (int i = 0; i < TM; i++) {
        int node = n0 + i * NG + ng;
        if (node < n) {
            float4 o = acc[i];
            if (BIAS) { o.x += bv.x; o.y += bv.y; o.z += bv.z; o.w += bv.w; }
            *(float4*)(OUT + (size_t)node * COUT + cg * 4) = o;
        }
    }
}

// ---------------------------------------------------------------------------
extern "C" void kernel_launch(void* const* d_in, const int* in_sizes, int n_in,
                              void* d_out, int out_size) {
    const float* x     = (const float*)d_in[0];
    const int*   ei    = (const int*)d_in[1];
    const float* W_enc = (const float*)d_in[2];
    const float* b_enc = (const float*)d_in[3];
    const float* W_dec = (const float*)d_in[4];
    const float* b_dec = (const float*)d_in[5];

    const int N = in_sizes[0] / 128;   // 100000
    const int E = in_sizes[1] / 2;     // 1600000
    const int* src = ei;
    const int* dst = ei + E;

    float* out_emb = (float*)d_out;                 // [N, 64]
    float* out_rec = out_emb + (size_t)N * 64;      // [N, 128]

    // real device addresses of scratch symbols (host shadow addr is invalid)
    float* hbuf = nullptr;
    cudaGetSymbolAddress((void**)&hbuf, g_h);
    int* cnt_dev = nullptr;
    cudaGetSymbolAddress((void**)&cnt_dev, g_cnt);

    // dynamic smem sizes (both > 48KB default cap)
    constexpr int SMEM_ENC = (128 * 64 + 128 * (128 + 4)) * 4;  // 100352
    constexpr int SMEM_DEC = (64 * 128 + 64 * (64 + 4)) * 4;    //  50176
    cudaFuncSetAttribute(k_gemm<128, 64, false>,
                         cudaFuncAttributeMaxDynamicSharedMemorySize, SMEM_ENC);
    cudaFuncSetAttribute(k_gemm<64, 128, true>,
                         cudaFuncAttributeMaxDynamicSharedMemorySize, SMEM_DEC);

    // lazily-created side stream + fork/join events (resource init only; every
    // call enqueues identical work). Non-blocking stream: no implicit legacy
    // sync, and graph capture propagates to it through the recorded events.
    static cudaStream_t s2 = nullptr;
    static cudaEvent_t evFork = nullptr, evJoin = nullptr;
    if (s2 == nullptr) {
        cudaStreamCreateWithFlags(&s2, cudaStreamNonBlocking);
        cudaEventCreateWithFlags(&evFork, cudaEventDisableTiming);
        cudaEventCreateWithFlags(&evJoin, cudaEventDisableTiming);
    }

    const int TB = 256;
    const int nbE = (E + TB - 1) / TB;

    // ---- fork: CSR build chain on side stream (independent of gemm1) ----
    cudaEventRecord(evFork, 0);
    cudaStreamWaitEvent(s2, evFork, 0);
    cudaMemsetAsync(cnt_dev, 0, (size_t)N * sizeof(int), s2);
    k_hist<<<nbE, TB, 0, s2>>>(dst, E);
    k_scan1<<<NB_SCAN, 1024, 0, s2>>>(N);           // also writes g_dinv
    k_scan2<<<1, 128, 0, s2>>>(NB_SCAN);
    k_scan3<<<NB_SCAN, 1024, 0, s2>>>(N);
    k_fill<<<nbE, TB, 0, s2>>>(src, dst, E);
    cudaEventRecord(evJoin, s2);

    // ---- concurrent on stream 0: gemm1 (128->64) ----
    k_gemm<128, 64, false><<<(N + 127) / 128, 256, SMEM_ENC>>>(x, W_enc, nullptr, hbuf, N);

    // ---- join, then serial tail ----
    cudaStreamWaitEvent(0, evJoin, 0);
    {
        int blocks = (N * 32 + TB - 1) / TB;   // warp per node
        k_agg64<true><<<blocks, TB>>>(hbuf, out_emb, b_enc, N);
        k_agg64<false><<<blocks, TB>>>(out_emb, hbuf, nullptr, N);
    }
    k_gemm<64, 128, true><<<(N + 63) / 64, 256, SMEM_DEC>>>(hbuf, W_dec, b_dec, out_rec, N);
}

// round 10
// speedup vs baseline: 1.1596x; 1.0165x over previous
#include <cuda_runtime.h>
#include <cuda_fp16.h>
#include <math.h>

// ---------------------------------------------------------------------------
// localAE: two stacked GCNConv layers.
//   loc_emb = GCN(x, W_enc, b_enc)          [N, 64]
//   loc_rec = GCN(loc_emb, W_dec, b_dec)    [N, 128]
// GCN(x) = D^-1/2 (A+I) D^-1/2 (x W) + b, deg = in-degree(dst) + 1
//
// Pipeline (linearity of aggregation used for the decoder):
//   g_hh  = fp16( x @ W_enc )                (gemm 128->64)   ── stream 0
//   CSR build (hist/scan/fill)               (independent)    ── side stream
//   emb   = dinv[d]*(sum h[s]*dinv[s] + h[d]*dinv[d]) + b_enc (fp16 gather)
//           -> fp32 out_emb + fp16 g_eh
//   g_h   = dinv[d]*(sum emb[s]*dinv[s] + emb[d]*dinv[d])     (fp16 gather)
//   rec   = g_h @ W_dec + b_dec              (gemm 64->128, fp32)
// Gather-side features are fp16 (read-once), accumulation is fp32.
// ---------------------------------------------------------------------------

#define NN   100000
#define EMAX 1600000
#define NB_SCAN ((NN + 1023) / 1024)   // 98

// scratch (static device globals: allocation-free)
__device__ float   g_h[(size_t)NN * 64];    // fp32 agg result (gemm2 input)
__device__ __half2 g_hh[(size_t)NN * 32];   // fp16 h = x@W_enc (gather source 1)
__device__ __half2 g_eh[(size_t)NN * 32];   // fp16 emb        (gather source 2)
__device__ float   g_dinv[NN];
__device__ int     g_cnt[NN];               // in-degree (without self loop)
__device__ int     g_ptr[NN];               // CSR row start
__device__ int     g_cur[NN];               // fill cursor
__device__ int     g_csr[EMAX];             // src ids grouped by dst
__device__ int     g_bsum[NB_SCAN];
__device__ int     g_boff[NB_SCAN];

// ---------------------------------------------------------------------------
__global__ void k_hist(const int* __restrict__ dst, int E) {
    int e = blockIdx.x * blockDim.x + threadIdx.x;
    if (e < E) atomicAdd(&g_cnt[dst[e]], 1);
}

// ---- scan stage 1 (shuffle-based) + dinv fused -----------------------------
__global__ void k_scan1(int n) {           // block = 1024
    int t = threadIdx.x;
    int lane = t & 31, wid = t >> 5;
    int gi = blockIdx.x * 1024 + t;
    int v = (gi < n) ? g_cnt[gi] : 0;
    if (gi < n) g_dinv[gi] = 1.0f / sqrtf((float)(v + 1));  // +1 self loop

    int x = v;
#pragma unroll
    for (int o = 1; o < 32; o <<= 1) {
        int y = __shfl_up_sync(0xffffffffu, x, o);
        if (lane >= o) x += y;
    }
    __shared__ int wsum[32];
    if (lane == 31) wsum[wid] = x;
    __syncthreads();
    if (wid == 0) {
        int s = wsum[lane];
#pragma unroll
        for (int o = 1; o < 32; o <<= 1) {
            int y = __shfl_up_sync(0xffffffffu, s, o);
            if (lane >= o) s += y;
        }
        wsum[lane] = s;
    }
    __syncthreads();
    int base = (wid > 0) ? wsum[wid - 1] : 0;
    int incl = x + base;
    if (gi < n) g_ptr[gi] = incl - v;        // exclusive
    if (t == 1023) g_bsum[blockIdx.x] = incl;
}

__global__ void k_scan2(int nb) {           // single block, 128 threads
    __shared__ int sh[128];
    int t = threadIdx.x;
    int v = (t < nb) ? g_bsum[t] : 0;
    sh[t] = v;
    __syncthreads();
#pragma unroll
    for (int off = 1; off < 128; off <<= 1) {
        int a = (t >= off) ? sh[t - off] : 0;
        __syncthreads();
        sh[t] += a;
        __syncthreads();
    }
    if (t < nb) g_boff[t] = sh[t] - v;       // exclusive
}

__global__ void k_scan3(int n) {            // block = 1024
    int gi = blockIdx.x * 1024 + threadIdx.x;
    if (gi < n) {
        int p = g_ptr[gi] + g_boff[blockIdx.x];
        g_ptr[gi] = p;
        g_cur[gi] = p;
    }
}

__global__ void k_fill(const int* __restrict__ src, const int* __restrict__ dst,
                       int E) {
    int e = blockIdx.x * blockDim.x + threadIdx.x;
    if (e < E) {
        int pos = atomicAdd(&g_cur[dst[e]], 1);
        g_csr[pos] = src[e];
    }
}

// ---------------------------------------------------------------------------
// CSR aggregation at 64 channels, fp16 gather source. One warp per node.
// Each lane-group (lane&15) handles 4 channels = 2 half2 (one uint2 = 8B);
// a full edge row = 16 lanes * 8B = 128B = one cache line.
// BIAS: add bias (layer 1). H16OUT: also emit fp16 copy (for next gather).
// ---------------------------------------------------------------------------
template<bool BIAS, bool H16OUT>
__global__ void k_agg64h(const __half2* __restrict__ feat,
                         float* __restrict__ out32,
                         __half2* __restrict__ out16,
                         const float* __restrict__ B, int n) {
    int w    = (blockIdx.x * blockDim.x + threadIdx.x) >> 5;   // node
    int lane = threadIdx.x & 31;
    if (w >= n) return;
    int c4   = lane & 15;        // 4-channel group -> half2 index c4*2
    int half = lane >> 4;        // 0 or 1
    int start = g_ptr[w];
    int cnt   = g_cnt[w];

    float4 acc = make_float4(0.f, 0.f, 0.f, 0.f);
    for (int k = half; k < cnt; k += 2) {
        int s = g_csr[start + k];
        float sc = g_dinv[s];
        uint2 raw = *(const uint2*)(feat + (size_t)s * 32 + c4 * 2);
        float2 fa = __half22float2(*(const __half2*)&raw.x);
        float2 fb = __half22float2(*(const __half2*)&raw.y);
        acc.x += fa.x * sc; acc.y += fa.y * sc;
        acc.z += fb.x * sc; acc.w += fb.y * sc;
    }
    if (half == 0) {             // self loop
        float sc = g_dinv[w];
        uint2 raw = *(const uint2*)(feat + (size_t)w * 32 + c4 * 2);
        float2 fa = __half22float2(*(const __half2*)&raw.x);
        float2 fb = __half22float2(*(const __half2*)&raw.y);
        acc.x += fa.x * sc; acc.y += fa.y * sc;
        acc.z += fb.x * sc; acc.w += fb.y * sc;
    }
    acc.x += __shfl_down_sync(0xffffffffu, acc.x, 16);
    acc.y += __shfl_down_sync(0xffffffffu, acc.y, 16);
    acc.z += __shfl_down_sync(0xffffffffu, acc.z, 16);
    acc.w += __shfl_down_sync(0xffffffffu, acc.w, 16);

    if (half == 0) {
        float dd = g_dinv[w];
        float4 o = make_float4(acc.x * dd, acc.y * dd, acc.z * dd, acc.w * dd);
        if (BIAS) {
            float4 bv = *(const float4*)(B + c4 * 4);
            o.x += bv.x; o.y += bv.y; o.z += bv.z; o.w += bv.w;
        }
        *(float4*)(out32 + (size_t)w * 64 + c4 * 4) = o;
        if (H16OUT) {
            uint2 raw;
            *(__half2*)&raw.x = __float22half2_rn(make_float2(o.x, o.y));
            *(__half2*)&raw.y = __float22half2_rn(make_float2(o.z, o.w));
            *(uint2*)(out16 + (size_t)w * 32 + c4 * 2) = raw;
        }
    }
}

// ---------------------------------------------------------------------------
// GEMM: OUT[n, COUT] = X[n, CIN] @ W[CIN, COUT] (+bias)
// Whole W and whole X block-tile staged into dynamic smem once; single
// __syncthreads; sync-free mainloop; interleaved node rows (conflict-free).
// H16OUT=true: store result as fp16 (half2 pairs) into OUT16 instead.
// Thread tile: 8 nodes x 4 channels.
// ---------------------------------------------------------------------------
template<int CIN, int COUT, bool BIAS, bool H16OUT>
__global__ void __launch_bounds__(256)
k_gemm(const float* __restrict__ X, const float* __restrict__ W,
       const float* __restrict__ B, float* __restrict__ OUT,
       __half2* __restrict__ OUT16, int n) {
    constexpr int TM = 8, TN = 4;
    constexpr int NT = 256;
    constexpr int CG = COUT / TN;        // 16 (enc) / 32 (dec)
    constexpr int NG = NT / CG;          // 16 / 8
    constexpr int BM = NG * TM;          // 128 / 64
    constexpr int XP = CIN + 4;          // 132 / 68  (both ≡ 4 mod 32 words)
    extern __shared__ float sm[];
    float* ws = sm;                      // CIN*COUT
    float* xs = sm + CIN * COUT;         // BM*XP

    const int t  = threadIdx.x;
    const int n0 = blockIdx.x * BM;

    // stage W (once)
#pragma unroll
    for (int i = t * 4; i < CIN * COUT; i += NT * 4)
        *(float4*)(ws + i) = *(const float4*)(W + i);

    // stage X block tile (once); tail rows clamped to n-1, stores guarded
    for (int i = t * 4; i < BM * CIN; i += NT * 4) {
        int r = i / CIN, col = i % CIN;
        int node = n0 + r;
        if (node > n - 1) node = n - 1;
        *(float4*)(xs + r * XP + col) =
            *(const float4*)(X + (size_t)node * CIN + col);
    }
    __syncthreads();

    const int cg = t % CG;
    const int ng = t / CG;

    float4 acc[TM];
#pragma unroll
    for (int i = 0; i < TM; i++) acc[i] = make_float4(0.f, 0.f, 0.f, 0.f);

#pragma unroll 2
    for (int k = 0; k < CIN; k += 4) {
        float4 w0 = *(const float4*)(ws + (k + 0) * COUT + cg * 4);
        float4 w1 = *(const float4*)(ws + (k + 1) * COUT + cg * 4);
        float4 w2 = *(const float4*)(ws + (k + 2) * COUT + cg * 4);
        float4 w3 = *(const float4*)(ws + (k + 3) * COUT + cg * 4);
#pragma unroll
        for (int i = 0; i < TM; i++) {
            float4 xv = *(const float4*)(xs + (i * NG + ng) * XP + k);
            acc[i].x += xv.x * w0.x + xv.y * w1.x + xv.z * w2.x + xv.w * w3.x;
            acc[i].y += xv.x * w0.y + xv.y * w1.y + xv.z * w2.y + xv.w * w3.y;
            acc[i].z += xv.x * w0.z + xv.y * w1.z + xv.z * w2.z + xv.w * w3.z;
            acc[i].w += xv.x * w0.w + xv.y * w1.w + xv.z * w2.w + xv.w * w3.w;
        }
    }

    float4 bv = make_float4(0.f, 0.f, 0.f, 0.f);
    if (BIAS) bv = *(const float4*)(B + cg * 4);
#pragma unroll
    for (int i = 0; i < TM; i++) {
        int node = n0 + i * NG + ng;
        if (node < n) {
            float4 o = acc[i];
            if (BIAS) { o.x += bv.x; o.y += bv.y; o.z += bv.z; o.w += bv.w; }
            if (H16OUT) {
                uint2 raw;
                *(__half2*)&raw.x = __float22half2_rn(make_float2(o.x, o.y));
                *(__half2*)&raw.y = __float22half2_rn(make_float2(o.z, o.w));
                *(uint2*)(OUT16 + (size_t)node * (COUT / 2) + cg * 2) = raw;
            } else {
                *(float4*)(OUT + (size_t)node * COUT + cg * 4) = o;
            }
        }
    }
}

// ---------------------------------------------------------------------------
extern "C" void kernel_launch(void* const* d_in, const int* in_sizes, int n_in,
                              void* d_out, int out_size) {
    const float* x     = (const float*)d_in[0];
    const int*   ei    = (const int*)d_in[1];
    const float* W_enc = (const float*)d_in[2];
    const float* b_enc = (const float*)d_in[3];
    const float* W_dec = (const float*)d_in[4];
    const float* b_dec = (const float*)d_in[5];

    const int N = in_sizes[0] / 128;   // 100000
    const int E = in_sizes[1] / 2;     // 1600000
    const int* src = ei;
    const int* dst = ei + E;

    float* out_emb = (float*)d_out;                 // [N, 64]
    float* out_rec = out_emb + (size_t)N * 64;      // [N, 128]

    // real device addresses of scratch symbols (host shadow addr is invalid)
    float* hbuf = nullptr;          cudaGetSymbolAddress((void**)&hbuf, g_h);
    __half2* hh = nullptr;          cudaGetSymbolAddress((void**)&hh, g_hh);
    __half2* eh = nullptr;          cudaGetSymbolAddress((void**)&eh, g_eh);
    int* cnt_dev = nullptr;         cudaGetSymbolAddress((void**)&cnt_dev, g_cnt);

    // dynamic smem sizes (both > 48KB default cap)
    constexpr int SMEM_ENC = (128 * 64 + 128 * (128 + 4)) * 4;  // 100352
    constexpr int SMEM_DEC = (64 * 128 + 64 * (64 + 4)) * 4;    //  50176
    cudaFuncSetAttribute(k_gemm<128, 64, false, true>,
                         cudaFuncAttributeMaxDynamicSharedMemorySize, SMEM_ENC);
    cudaFuncSetAttribute(k_gemm<64, 128, true, false>,
                         cudaFuncAttributeMaxDynamicSharedMemorySize, SMEM_DEC);

    // lazily-created side stream + fork/join events (resource init only; every
    // call enqueues identical work). If creation ever fails, fall back to the
    // default stream (serial, still correct).
    static cudaStream_t s2 = nullptr;
    static cudaEvent_t evFork = nullptr, evJoin = nullptr;
    static bool forkOK = false;
    static bool inited = false;
    if (!inited) {
        inited = true;
        if (cudaStreamCreateWithFlags(&s2, cudaStreamNonBlocking) == cudaSuccess &&
            cudaEventCreateWithFlags(&evFork, cudaEventDisableTiming) == cudaSuccess &&
            cudaEventCreateWithFlags(&evJoin, cudaEventDisableTiming) == cudaSuccess)
            forkOK = true;
    }

    const int TB = 256;
    const int nbE = (E + TB - 1) / TB;
    cudaStream_t sb = forkOK ? s2 : (cudaStream_t)0;   // build stream

    // ---- fork: CSR build chain (independent of gemm1) ----
    if (forkOK) {
        cudaEventRecord(evFork, 0);
        cudaStreamWaitEvent(sb, evFork, 0);
    }
    cudaMemsetAsync(cnt_dev, 0, (size_t)N * sizeof(int), sb);
    k_hist<<<nbE, TB, 0, sb>>>(dst, E);
    k_scan1<<<NB_SCAN, 1024, 0, sb>>>(N);           // also writes g_dinv
    k_scan2<<<1, 128, 0, sb>>>(NB_SCAN);
    k_scan3<<<NB_SCAN, 1024, 0, sb>>>(N);
    k_fill<<<nbE, TB, 0, sb>>>(src, dst, E);
    if (forkOK) cudaEventRecord(evJoin, sb);

    // ---- concurrent on stream 0: gemm1 (128->64), fp16 output ----
    k_gemm<128, 64, false, true><<<(N + 127) / 128, 256, SMEM_ENC>>>(
        x, W_enc, nullptr, nullptr, hh, N);

    // ---- join, then serial tail ----
    if (forkOK) cudaStreamWaitEvent(0, evJoin, 0);
    {
        int blocks = (N * 32 + TB - 1) / TB;   // warp per node
        // agg1: gather fp16 h -> fp32 out_emb + fp16 copy for agg2
        k_agg64h<true, true><<<blocks, TB>>>(hh, out_emb, eh, b_enc, N);
        // agg2: gather fp16 emb -> fp32 hbuf (gemm2 input)
        k_agg64h<false, false><<<blocks, TB>>>(eh, hbuf, nullptr, nullptr, N);
    }
    k_gemm<64, 128, true, false><<<(N + 63) / 64, 256, SMEM_DEC>>>(
        hbuf, W_dec, b_dec, out_rec, nullptr, N);
}

// round 11
// speedup vs baseline: 1.5121x; 1.3040x over previous
#include <cuda_runtime.h>
#include <cuda_fp16.h>
#include <math.h>

// ---------------------------------------------------------------------------
// localAE: two stacked GCNConv layers.
//   loc_emb = GCN(x, W_enc, b_enc)          [N, 64]
//   loc_rec = GCN(loc_emb, W_dec, b_dec)    [N, 128]
// GCN(x) = D^-1/2 (A+I) D^-1/2 (x W) + b, deg = in-degree(dst) + 1
//
// Pipeline (linearity of aggregation used for the decoder):
//   g_hh  = fp16( x @ W_enc )              (HMMA gemm 128->64)  ── stream 0
//   CSR build (hist/scan/fill)             (independent)        ── side stream
//   emb   = agg(g_hh) + b_enc  -> fp32 out_emb + fp16 g_eh      (fp16 gather)
//   g_hh  = fp16( agg(g_eh) )                                   (fp16 gather)
//   rec   = g_hh @ W_dec + b_dec           (HMMA gemm 64->128, fp32 out)
// GEMMs: warp-level mma.sync.m16n8k16 (fp16 in, fp32 accumulate);
// A/B staged in padded smem, ldmatrix conflict-free (row stride ≡ 16 mod 128B).
// ---------------------------------------------------------------------------

#define NN   100000
#define EMAX 1600000
#define NB_SCAN ((NN + 1023) / 1024)   // 98

// scratch (static device globals: allocation-free)
__device__ __half2 g_hh[(size_t)NN * 32];   // fp16 features (reused both layers)
__device__ __half2 g_eh[(size_t)NN * 32];   // fp16 emb (gather source 2)
__device__ float   g_dinv[NN];
__device__ int     g_cnt[NN];               // in-degree (without self loop)
__device__ int     g_ptr[NN];               // CSR row start
__device__ int     g_cur[NN];               // fill cursor
__device__ int     g_csr[EMAX];             // src ids grouped by dst
__device__ int     g_bsum[NB_SCAN];
__device__ int     g_boff[NB_SCAN];

// ---------------------------------------------------------------------------
__global__ void k_hist(const int* __restrict__ dst, int E) {
    int e = blockIdx.x * blockDim.x + threadIdx.x;
    if (e < E) atomicAdd(&g_cnt[dst[e]], 1);
}

// ---- scan stage 1 (shuffle-based) + dinv fused -----------------------------
__global__ void k_scan1(int n) {           // block = 1024
    int t = threadIdx.x;
    int lane = t & 31, wid = t >> 5;
    int gi = blockIdx.x * 1024 + t;
    int v = (gi < n) ? g_cnt[gi] : 0;
    if (gi < n) g_dinv[gi] = 1.0f / sqrtf((float)(v + 1));  // +1 self loop

    int x = v;
#pragma unroll
    for (int o = 1; o < 32; o <<= 1) {
        int y = __shfl_up_sync(0xffffffffu, x, o);
        if (lane >= o) x += y;
    }
    __shared__ int wsum[32];
    if (lane == 31) wsum[wid] = x;
    __syncthreads();
    if (wid == 0) {
        int s = wsum[lane];
#pragma unroll
        for (int o = 1; o < 32; o <<= 1) {
            int y = __shfl_up_sync(0xffffffffu, s, o);
            if (lane >= o) s += y;
        }
        wsum[lane] = s;
    }
    __syncthreads();
    int base = (wid > 0) ? wsum[wid - 1] : 0;
    int incl = x + base;
    if (gi < n) g_ptr[gi] = incl - v;        // exclusive
    if (t == 1023) g_bsum[blockIdx.x] = incl;
}

__global__ void k_scan2(int nb) {           // single block, 128 threads
    __shared__ int sh[128];
    int t = threadIdx.x;
    int v = (t < nb) ? g_bsum[t] : 0;
    sh[t] = v;
    __syncthreads();
#pragma unroll
    for (int off = 1; off < 128; off <<= 1) {
        int a = (t >= off) ? sh[t - off] : 0;
        __syncthreads();
        sh[t] += a;
        __syncthreads();
    }
    if (t < nb) g_boff[t] = sh[t] - v;       // exclusive
}

__global__ void k_scan3(int n) {            // block = 1024
    int gi = blockIdx.x * 1024 + threadIdx.x;
    if (gi < n) {
        int p = g_ptr[gi] + g_boff[blockIdx.x];
        g_ptr[gi] = p;
        g_cur[gi] = p;
    }
}

__global__ void k_fill(const int* __restrict__ src, const int* __restrict__ dst,
                       int E) {
    int e = blockIdx.x * blockDim.x + threadIdx.x;
    if (e < E) {
        int pos = atomicAdd(&g_cur[dst[e]], 1);
        g_csr[pos] = src[e];
    }
}

// ---------------------------------------------------------------------------
// CSR aggregation at 64 channels, fp16 gather source. One warp per node.
// W32: write fp32 result. W16: write fp16 result. BIAS: add bias (fp32 path).
// ---------------------------------------------------------------------------
template<bool BIAS, bool W32, bool W16>
__global__ void k_agg64h(const __half2* __restrict__ feat,
                         float* __restrict__ out32,
                         __half2* __restrict__ out16,
                         const float* __restrict__ B, int n) {
    int w    = (blockIdx.x * blockDim.x + threadIdx.x) >> 5;   // node
    int lane = threadIdx.x & 31;
    if (w >= n) return;
    int c4   = lane & 15;        // 4-channel group -> half2 index c4*2
    int half = lane >> 4;        // 0 or 1
    int start = g_ptr[w];
    int cnt   = g_cnt[w];

    float4 acc = make_float4(0.f, 0.f, 0.f, 0.f);
    for (int k = half; k < cnt; k += 2) {
        int s = g_csr[start + k];
        float sc = g_dinv[s];
        uint2 raw = *(const uint2*)(feat + (size_t)s * 32 + c4 * 2);
        float2 fa = __half22float2(*(const __half2*)&raw.x);
        float2 fb = __half22float2(*(const __half2*)&raw.y);
        acc.x += fa.x * sc; acc.y += fa.y * sc;
        acc.z += fb.x * sc; acc.w += fb.y * sc;
    }
    if (half == 0) {             // self loop
        float sc = g_dinv[w];
        uint2 raw = *(const uint2*)(feat + (size_t)w * 32 + c4 * 2);
        float2 fa = __half22float2(*(const __half2*)&raw.x);
        float2 fb = __half22float2(*(const __half2*)&raw.y);
        acc.x += fa.x * sc; acc.y += fa.y * sc;
        acc.z += fb.x * sc; acc.w += fb.y * sc;
    }
    acc.x += __shfl_down_sync(0xffffffffu, acc.x, 16);
    acc.y += __shfl_down_sync(0xffffffffu, acc.y, 16);
    acc.z += __shfl_down_sync(0xffffffffu, acc.z, 16);
    acc.w += __shfl_down_sync(0xffffffffu, acc.w, 16);

    if (half == 0) {
        float dd = g_dinv[w];
        float4 o = make_float4(acc.x * dd, acc.y * dd, acc.z * dd, acc.w * dd);
        if (BIAS) {
            float4 bv = *(const float4*)(B + c4 * 4);
            o.x += bv.x; o.y += bv.y; o.z += bv.z; o.w += bv.w;
        }
        if (W32)
            *(float4*)(out32 + (size_t)w * 64 + c4 * 4) = o;
        if (W16) {
            uint2 raw;
            *(__half2*)&raw.x = __float22half2_rn(make_float2(o.x, o.y));
            *(__half2*)&raw.y = __float22half2_rn(make_float2(o.z, o.w));
            *(uint2*)(out16 + (size_t)w * 32 + c4 * 2) = raw;
        }
    }
}

// ---------------------------------------------------------------------------
// Tensor-core GEMM: OUT[n, COUT] = X[n, CIN] @ W[CIN, COUT] (+bias)
// fp16 inputs (converted in smem staging), fp32 accumulate (mma.m16n8k16).
// 8 warps; warp tile 32x32; A padded CIN+8, B padded COUT+8 (ldmatrix
// row stride ≡ 16 mod 128 bytes -> conflict-free).
// AH16: X is fp16 (half2). OH16: write fp16 to OUT16, else fp32 (+bias).
// ---------------------------------------------------------------------------
#define LDSM_X4(f, addr) \
    asm volatile("ldmatrix.sync.aligned.m8n8.x4.shared.b16 {%0,%1,%2,%3}, [%4];" \
        : "=r"(f.x), "=r"(f.y), "=r"(f.z), "=r"(f.w) : "r"(addr))
#define LDSM_X4T(f, addr) \
    asm volatile("ldmatrix.sync.aligned.m8n8.x4.trans.shared.b16 {%0,%1,%2,%3}, [%4];" \
        : "=r"(f.x), "=r"(f.y), "=r"(f.z), "=r"(f.w) : "r"(addr))
#define MMA16816(d, a, b0, b1) \
    asm volatile("mma.sync.aligned.m16n8k16.row.col.f32.f16.f16.f32 " \
        "{%0,%1,%2,%3}, {%4,%5,%6,%7}, {%8,%9}, {%0,%1,%2,%3};" \
        : "+f"(d[0]), "+f"(d[1]), "+f"(d[2]), "+f"(d[3]) \
        : "r"(a.x), "r"(a.y), "r"(a.z), "r"(a.w), "r"(b0), "r"(b1))

template<int CIN, int COUT, bool BIAS, bool AH16, bool OH16>
__global__ void __launch_bounds__(256)
k_gemm_t(const void* __restrict__ Xv, const float* __restrict__ W,
         const float* __restrict__ Bb, float* __restrict__ OUT,
         __half2* __restrict__ OUT16, int n) {
    constexpr int WN = COUT / 32;      // 2 (enc) / 4 (dec)
    constexpr int WM = 8 / WN;         // 4 / 2
    constexpr int BM = WM * 32;        // 128 / 64
    constexpr int AP = CIN + 8;        // padded A row (halves)
    constexpr int BP = COUT + 8;       // padded B row (halves)
    extern __shared__ __half smh[];
    __half* As = smh;                  // BM * AP
    __half* Bs = smh + BM * AP;        // CIN * BP

    const int t  = threadIdx.x;
    const int n0 = blockIdx.x * BM;

    // stage W -> fp16 smem
    for (int i = t * 4; i < CIN * COUT; i += 256 * 4) {
        int r = i / COUT, c = i % COUT;
        float4 v = *(const float4*)(W + i);
        uint2 raw;
        *(__half2*)&raw.x = __floats2half2_rn(v.x, v.y);
        *(__half2*)&raw.y = __floats2half2_rn(v.z, v.w);
        *(uint2*)(Bs + r * BP + c) = raw;
    }
    // stage A -> fp16 smem (tail rows clamped, stores guarded in epilogue)
    if (AH16) {
        const __half2* X = (const __half2*)Xv;
        for (int i = t * 4; i < BM * CIN; i += 256 * 4) {
            int r = i / CIN, c = i % CIN;
            int node = n0 + r; if (node > n - 1) node = n - 1;
            uint2 raw = *(const uint2*)(X + (size_t)node * (CIN / 2) + c / 2);
            *(uint2*)(As + r * AP + c) = raw;
        }
    } else {
        const float* X = (const float*)Xv;
        for (int i = t * 4; i < BM * CIN; i += 256 * 4) {
            int r = i / CIN, c = i % CIN;
            int node = n0 + r; if (node > n - 1) node = n - 1;
            float4 v = *(const float4*)(X + (size_t)node * CIN + c);
            uint2 raw;
            *(__half2*)&raw.x = __floats2half2_rn(v.x, v.y);
            *(__half2*)&raw.y = __floats2half2_rn(v.z, v.w);
            *(uint2*)(As + r * AP + c) = raw;
        }
    }
    __syncthreads();

    const int w = t >> 5, lane = t & 31;
    const int wm = w / WN, wn = w % WN;

    float d[2][4][4];
#pragma unroll
    for (int mi = 0; mi < 2; mi++)
#pragma unroll
        for (int ni = 0; ni < 4; ni++)
#pragma unroll
            for (int j = 0; j < 4; j++) d[mi][ni][j] = 0.f;

    unsigned a_base = (unsigned)__cvta_generic_to_shared(
        As + (wm * 32 + (lane & 15)) * AP + (lane >> 4) * 8);
    unsigned b_base = (unsigned)__cvta_generic_to_shared(
        Bs + (lane & 15) * BP + wn * 32 + (lane >> 4) * 8);

#pragma unroll
    for (int k0 = 0; k0 < CIN; k0 += 16) {
        uint4 A0, A1, B0, B1;
        LDSM_X4(A0, a_base + k0 * 2);
        LDSM_X4(A1, a_base + k0 * 2 + 16 * AP * 2);
        LDSM_X4T(B0, b_base + k0 * BP * 2);          // n-tiles 0,1
        LDSM_X4T(B1, b_base + k0 * BP * 2 + 16 * 2); // n-tiles 2,3
        MMA16816(d[0][0], A0, B0.x, B0.y);
        MMA16816(d[0][1], A0, B0.z, B0.w);
        MMA16816(d[0][2], A0, B1.x, B1.y);
        MMA16816(d[0][3], A0, B1.z, B1.w);
        MMA16816(d[1][0], A1, B0.x, B0.y);
        MMA16816(d[1][1], A1, B0.z, B0.w);
        MMA16816(d[1][2], A1, B1.x, B1.y);
        MMA16816(d[1][3], A1, B1.z, B1.w);
    }

    // epilogue: thread owns rows (lane>>2, +8) cols (lane&3)*2..+1 per tile
    const int r0 = lane >> 2;
    const int cc = (lane & 3) * 2;
#pragma unroll
    for (int mi = 0; mi < 2; mi++) {
#pragma unroll
        for (int ni = 0; ni < 4; ni++) {
            int col = wn * 32 + ni * 8 + cc;
#pragma unroll
            for (int h = 0; h < 2; h++) {            // row halves (+0, +8)
                int node = n0 + wm * 32 + mi * 16 + h * 8 + r0;
                if (node < n) {
                    float v0 = d[mi][ni][h * 2 + 0];
                    float v1 = d[mi][ni][h * 2 + 1];
                    if (OH16) {
                        *(__half2*)(OUT16 + (size_t)node * (COUT / 2) + col / 2)
                            = __floats2half2_rn(v0, v1);
                    } else {
                        if (BIAS) {
                            float2 bv = *(const float2*)(Bb + col);
                            v0 += bv.x; v1 += bv.y;
                        }
                        float2 o = make_float2(v0, v1);
                        *(float2*)(OUT + (size_t)node * COUT + col) = o;
                    }
                }
            }
        }
    }
}

// ---------------------------------------------------------------------------
extern "C" void kernel_launch(void* const* d_in, const int* in_sizes, int n_in,
                              void* d_out, int out_size) {
    const float* x     = (const float*)d_in[0];
    const int*   ei    = (const int*)d_in[1];
    const float* W_enc = (const float*)d_in[2];
    const float* b_enc = (const float*)d_in[3];
    const float* W_dec = (const float*)d_in[4];
    const float* b_dec = (const float*)d_in[5];

    const int N = in_sizes[0] / 128;   // 100000
    const int E = in_sizes[1] / 2;     // 1600000
    const int* src = ei;
    const int* dst = ei + E;

    float* out_emb = (float*)d_out;                 // [N, 64]
    float* out_rec = out_emb + (size_t)N * 64;      // [N, 128]

    // real device addresses of scratch symbols (host shadow addr is invalid)
    __half2* hh = nullptr;          cudaGetSymbolAddress((void**)&hh, g_hh);
    __half2* eh = nullptr;          cudaGetSymbolAddress((void**)&eh, g_eh);
    int* cnt_dev = nullptr;         cudaGetSymbolAddress((void**)&cnt_dev, g_cnt);

    // dynamic smem: enc 53248 B (> 48K default), dec 26624 B
    constexpr int SMEM_ENC = (128 * (128 + 8) + 128 * (64 + 8)) * 2;   // 53248
    constexpr int SMEM_DEC = (64 * (64 + 8) + 64 * (128 + 8)) * 2;     // 26624
    cudaFuncSetAttribute(k_gemm_t<128, 64, false, false, true>,
                         cudaFuncAttributeMaxDynamicSharedMemorySize, SMEM_ENC);
    cudaFuncSetAttribute(k_gemm_t<64, 128, true, true, false>,
                         cudaFuncAttributeMaxDynamicSharedMemorySize, SMEM_DEC);

    // lazily-created side stream + fork/join events (resource init only; every
    // call enqueues identical work). Fallback: default stream (still correct).
    static cudaStream_t s2 = nullptr;
    static cudaEvent_t evFork = nullptr, evJoin = nullptr;
    static bool forkOK = false;
    static bool inited = false;
    if (!inited) {
        inited = true;
        if (cudaStreamCreateWithFlags(&s2, cudaStreamNonBlocking) == cudaSuccess &&
            cudaEventCreateWithFlags(&evFork, cudaEventDisableTiming) == cudaSuccess &&
            cudaEventCreateWithFlags(&evJoin, cudaEventDisableTiming) == cudaSuccess)
            forkOK = true;
    }

    const int TB = 256;
    const int nbE = (E + TB - 1) / TB;
    cudaStream_t sb = forkOK ? s2 : (cudaStream_t)0;   // build stream

    // ---- fork: CSR build chain (independent of gemm1) ----
    if (forkOK) {
        cudaEventRecord(evFork, 0);
        cudaStreamWaitEvent(sb, evFork, 0);
    }
    cudaMemsetAsync(cnt_dev, 0, (size_t)N * sizeof(int), sb);
    k_hist<<<nbE, TB, 0, sb>>>(dst, E);
    k_scan1<<<NB_SCAN, 1024, 0, sb>>>(N);           // also writes g_dinv
    k_scan2<<<1, 128, 0, sb>>>(NB_SCAN);
    k_scan3<<<NB_SCAN, 1024, 0, sb>>>(N);
    k_fill<<<nbE, TB, 0, sb>>>(src, dst, E);
    if (forkOK) cudaEventRecord(evJoin, sb);

    // ---- concurrent on stream 0: gemm1 (128->64, HMMA), fp16 output ----
    k_gemm_t<128, 64, false, false, true><<<(N + 127) / 128, 256, SMEM_ENC>>>(
        x, W_enc, nullptr, nullptr, hh, N);

    // ---- join, then serial tail ----
    if (forkOK) cudaStreamWaitEvent(0, evJoin, 0);
    {
        int blocks = (N * 32 + TB - 1) / TB;   // warp per node
        // agg1: gather fp16 h -> fp32 out_emb + fp16 copy for agg2
        k_agg64h<true, true, true><<<blocks, TB>>>(hh, out_emb, eh, b_enc, N);
        // agg2: gather fp16 emb -> fp16 (g_hh reused; gemm2 input)
        k_agg64h<false, false, true><<<blocks, TB>>>(eh, nullptr, hh, nullptr, N);
    }
    // gemm2 (64->128, HMMA), fp32 output + bias
    k_gemm_t<64, 128, true, true, false><<<(N + 63) / 64, 256, SMEM_DEC>>>(
        hh, W_dec, b_dec, out_rec, nullptr, N);
}

// round 12
// speedup vs baseline: 1.6029x; 1.0600x over previous
#include <cuda_runtime.h>
#include <cuda_fp16.h>
#include <math.h>

// ---------------------------------------------------------------------------
// localAE: two stacked GCNConv layers.
//   loc_emb = GCN(x, W_enc, b_enc)          [N, 64]
//   loc_rec = GCN(loc_emb, W_dec, b_dec)    [N, 128]
// GCN(x) = D^-1/2 (A+I) D^-1/2 (x W) + b, deg = in-degree(dst) + 1
//
// Pipeline (linearity of aggregation used for the decoder):
//   g_hh  = fp16( x @ W_enc )              (HMMA gemm 128->64)  ── stream 0
//   CSR build (hist/scan/fill)             (independent)        ── side stream
//   emb   = agg(g_hh) + b_enc  -> fp32 out_emb
//           + fp16 g_eh PRE-SCALED by dinv[w]                    (fp16 gather)
//   g_hh  = fp16( agg_prescaled(g_eh) )                          (pure-sum gather)
//   rec   = g_hh @ W_dec + b_dec           (HMMA gemm 64->128, fp32 out)
// ---------------------------------------------------------------------------

#define NN   100000
#define EMAX 1600000
#define NB_SCAN ((NN + 1023) / 1024)   // 98

// scratch (static device globals: allocation-free)
__device__ __half2 g_hh[(size_t)NN * 32];   // fp16 features (reused both layers)
__device__ __half2 g_eh[(size_t)NN * 32];   // fp16 emb*dinv (gather source 2)
__device__ float   g_dinv[NN];
__device__ int     g_cnt[NN];               // in-degree (without self loop)
__device__ int     g_ptr[NN];               // CSR row start
__device__ int     g_cur[NN];               // fill cursor
__device__ int     g_csr[EMAX];             // src ids grouped by dst
__device__ int     g_bsum[NB_SCAN];

// ---------------------------------------------------------------------------
// histogram of dst, int4-vectorized
__global__ void k_hist(const int* __restrict__ dst, int E) {
    int i = blockIdx.x * blockDim.x + threadIdx.x;
    int E4 = E >> 2;
    if (i < E4) {
        int4 v = *(const int4*)(dst + i * 4);
        atomicAdd(&g_cnt[v.x], 1);
        atomicAdd(&g_cnt[v.y], 1);
        atomicAdd(&g_cnt[v.z], 1);
        atomicAdd(&g_cnt[v.w], 1);
    } else {
        int e = E4 * 4 + (i - E4);
        if (e < E) atomicAdd(&g_cnt[dst[e]], 1);
    }
}

// ---- scan stage 1 (shuffle-based) + dinv fused -----------------------------
__global__ void k_scan1(int n) {           // block = 1024
    int t = threadIdx.x;
    int lane = t & 31, wid = t >> 5;
    int gi = blockIdx.x * 1024 + t;
    int v = (gi < n) ? g_cnt[gi] : 0;
    if (gi < n) g_dinv[gi] = 1.0f / sqrtf((float)(v + 1));  // +1 self loop

    int x = v;
#pragma unroll
    for (int o = 1; o < 32; o <<= 1) {
        int y = __shfl_up_sync(0xffffffffu, x, o);
        if (lane >= o) x += y;
    }
    __shared__ int wsum[32];
    if (lane == 31) wsum[wid] = x;
    __syncthreads();
    if (wid == 0) {
        int s = wsum[lane];
#pragma unroll
        for (int o = 1; o < 32; o <<= 1) {
            int y = __shfl_up_sync(0xffffffffu, s, o);
            if (lane >= o) s += y;
        }
        wsum[lane] = s;
    }
    __syncthreads();
    int base = (wid > 0) ? wsum[wid - 1] : 0;
    int incl = x + base;
    if (gi < n) g_ptr[gi] = incl - v;        // exclusive
    if (t == 1023) g_bsum[blockIdx.x] = incl;
}

// ---- merged scan stages 2+3: each block sums preceding block totals --------
__global__ void k_scan23(int n) {           // block = 1024, grid = NB_SCAN
    __shared__ int boff;
    int t = threadIdx.x;
    if (t < 32) {
        int sum = 0;
        for (int i = t; i < (int)blockIdx.x; i += 32) sum += g_bsum[i];
#pragma unroll
        for (int o = 16; o; o >>= 1) sum += __shfl_down_sync(0xffffffffu, sum, o);
        if (t == 0) boff = sum;
    }
    __syncthreads();
    int gi = blockIdx.x * 1024 + t;
    if (gi < n) {
        int p = g_ptr[gi] + boff;
        g_ptr[gi] = p;
        g_cur[gi] = p;
    }
}

// CSR fill, int4-vectorized edge loads
__global__ void k_fill(const int* __restrict__ src, const int* __restrict__ dst,
                       int E) {
    int i = blockIdx.x * blockDim.x + threadIdx.x;
    int E4 = E >> 2;
    if (i < E4) {
        int4 s = *(const int4*)(src + i * 4);
        int4 d = *(const int4*)(dst + i * 4);
        g_csr[atomicAdd(&g_cur[d.x], 1)] = s.x;
        g_csr[atomicAdd(&g_cur[d.y], 1)] = s.y;
        g_csr[atomicAdd(&g_cur[d.z], 1)] = s.z;
        g_csr[atomicAdd(&g_cur[d.w], 1)] = s.w;
    } else {
        int e = E4 * 4 + (i - E4);
        if (e < E) g_csr[atomicAdd(&g_cur[dst[e]], 1)] = src[e];
    }
}

// ---------------------------------------------------------------------------
// CSR aggregation at 64 channels, fp16 gather source. One warp per node.
// Edge loop unrolled by 2 (two independent gathers in flight per half-warp).
// PRE:   features are pre-scaled by dinv[s] -> pure sum (no dinv gather).
// BIAS:  add bias (fp32 path). W32: write fp32. W16: write fp16 copy.
// W16PRE: pre-scale the fp16 copy by dinv[w] (feeds the next PRE gather).
// ---------------------------------------------------------------------------
template<bool PRE, bool BIAS, bool W32, bool W16, bool W16PRE>
__global__ void k_agg64h(const __half2* __restrict__ feat,
                         float* __restrict__ out32,
                         __half2* __restrict__ out16,
                         const float* __restrict__ B, int n) {
    int w    = (blockIdx.x * blockDim.x + threadIdx.x) >> 5;   // node
    int lane = threadIdx.x & 31;
    if (w >= n) return;
    int c4   = lane & 15;        // 4-channel group -> half2 index c4*2
    int half = lane >> 4;        // 0 or 1
    int start = g_ptr[w];
    int cnt   = g_cnt[w];

    float4 acc = make_float4(0.f, 0.f, 0.f, 0.f);
    int k = half;
    for (; k + 2 < cnt; k += 4) {          // edges k and k+2
        int s0 = g_csr[start + k];
        int s1 = g_csr[start + k + 2];
        uint2 r0 = *(const uint2*)(feat + (size_t)s0 * 32 + c4 * 2);
        uint2 r1 = *(const uint2*)(feat + (size_t)s1 * 32 + c4 * 2);
        float sc0 = PRE ? 1.0f : g_dinv[s0];
        float sc1 = PRE ? 1.0f : g_dinv[s1];
        float2 a0 = __half22float2(*(const __half2*)&r0.x);
        float2 b0 = __half22float2(*(const __half2*)&r0.y);
        float2 a1 = __half22float2(*(const __half2*)&r1.x);
        float2 b1 = __half22float2(*(const __half2*)&r1.y);
        if (PRE) {
            acc.x += a0.x + a1.x; acc.y += a0.y + a1.y;
            acc.z += b0.x + b1.x; acc.w += b0.y + b1.y;
        } else {
            acc.x += a0.x * sc0 + a1.x * sc1; acc.y += a0.y * sc0 + a1.y * sc1;
            acc.z += b0.x * sc0 + b1.x * sc1; acc.w += b0.y * sc0 + b1.y * sc1;
        }
    }
    if (k < cnt) {                          // remainder edge
        int s = g_csr[start + k];
        float sc = PRE ? 1.0f : g_dinv[s];
        uint2 raw = *(const uint2*)(feat + (size_t)s * 32 + c4 * 2);
        float2 fa = __half22float2(*(const __half2*)&raw.x);
        float2 fb = __half22float2(*(const __half2*)&raw.y);
        acc.x += fa.x * sc; acc.y += fa.y * sc;
        acc.z += fb.x * sc; acc.w += fb.y * sc;
    }
    if (half == 0) {                        // self loop (PRE: already scaled)
        float sc = PRE ? 1.0f : g_dinv[w];
        uint2 raw = *(const uint2*)(feat + (size_t)w * 32 + c4 * 2);
        float2 fa = __half22float2(*(const __half2*)&raw.x);
        float2 fb = __half22float2(*(const __half2*)&raw.y);
        acc.x += fa.x * sc; acc.y += fa.y * sc;
        acc.z += fb.x * sc; acc.w += fb.y * sc;
    }
    acc.x += __shfl_down_sync(0xffffffffu, acc.x, 16);
    acc.y += __shfl_down_sync(0xffffffffu, acc.y, 16);
    acc.z += __shfl_down_sync(0xffffffffu, acc.z, 16);
    acc.w += __shfl_down_sync(0xffffffffu, acc.w, 16);

    if (half == 0) {
        float dd = g_dinv[w];
        float4 o = make_float4(acc.x * dd, acc.y * dd, acc.z * dd, acc.w * dd);
        if (BIAS) {
            float4 bv = *(const float4*)(B + c4 * 4);
            o.x += bv.x; o.y += bv.y; o.z += bv.z; o.w += bv.w;
        }
        if (W32)
            *(float4*)(out32 + (size_t)w * 64 + c4 * 4) = o;
        if (W16) {
            float s16 = W16PRE ? dd : 1.0f;
            uint2 raw;
            *(__half2*)&raw.x = __float22half2_rn(make_float2(o.x * s16, o.y * s16));
            *(__half2*)&raw.y = __float22half2_rn(make_float2(o.z * s16, o.w * s16));
            *(uint2*)(out16 + (size_t)w * 32 + c4 * 2) = raw;
        }
    }
}

// ---------------------------------------------------------------------------
// Tensor-core GEMM: OUT[n, COUT] = X[n, CIN] @ W[CIN, COUT] (+bias)
// fp16 inputs (converted in smem staging), fp32 accumulate (mma.m16n8k16).
// 8 warps; warp tile 32x32; A padded CIN+8, B padded COUT+8 (ldmatrix
// row stride ≡ 16 mod 128 bytes -> conflict-free).
// AH16: X is fp16 (half2). OH16: write fp16 to OUT16, else fp32 (+bias).
// ---------------------------------------------------------------------------
#define LDSM_X4(f, addr) \
    asm volatile("ldmatrix.sync.aligned.m8n8.x4.shared.b16 {%0,%1,%2,%3}, [%4];" \
        : "=r"(f.x), "=r"(f.y), "=r"(f.z), "=r"(f.w) : "r"(addr))
#define LDSM_X4T(f, addr) \
    asm volatile("ldmatrix.sync.aligned.m8n8.x4.trans.shared.b16 {%0,%1,%2,%3}, [%4];" \
        : "=r"(f.x), "=r"(f.y), "=r"(f.z), "=r"(f.w) : "r"(addr))
#define MMA16816(d, a, b0, b1) \
    asm volatile("mma.sync.aligned.m16n8k16.row.col.f32.f16.f16.f32 " \
        "{%0,%1,%2,%3}, {%4,%5,%6,%7}, {%8,%9}, {%0,%1,%2,%3};" \
        : "+f"(d[0]), "+f"(d[1]), "+f"(d[2]), "+f"(d[3]) \
        : "r"(a.x), "r"(a.y), "r"(a.z), "r"(a.w), "r"(b0), "r"(b1))

template<int CIN, int COUT, bool BIAS, bool AH16, bool OH16>
__global__ void __launch_bounds__(256)
k_gemm_t(const void* __restrict__ Xv, const float* __restrict__ W,
         const float* __restrict__ Bb, float* __restrict__ OUT,
         __half2* __restrict__ OUT16, int n) {
    constexpr int WN = COUT / 32;      // 2 (enc) / 4 (dec)
    constexpr int WM = 8 / WN;         // 4 / 2
    constexpr int BM = WM * 32;        // 128 / 64
    constexpr int AP = CIN + 8;        // padded A row (halves)
    constexpr int BP = COUT + 8;       // padded B row (halves)
    extern __shared__ __half smh[];
    __half* As = smh;                  // BM * AP
    __half* Bs = smh + BM * AP;        // CIN * BP

    const int t  = threadIdx.x;
    const int n0 = blockIdx.x * BM;

    // stage W -> fp16 smem
    for (int i = t * 4; i < CIN * COUT; i += 256 * 4) {
        int r = i / COUT, c = i % COUT;
        float4 v = *(const float4*)(W + i);
        uint2 raw;
        *(__half2*)&raw.x = __floats2half2_rn(v.x, v.y);
        *(__half2*)&raw.y = __floats2half2_rn(v.z, v.w);
        *(uint2*)(Bs + r * BP + c) = raw;
    }
    // stage A -> fp16 smem (tail rows clamped, stores guarded in epilogue)
    if (AH16) {
        const __half2* X = (const __half2*)Xv;
        for (int i = t * 4; i < BM * CIN; i += 256 * 4) {
            int r = i / CIN, c = i % CIN;
            int node = n0 + r; if (node > n - 1) node = n - 1;
            uint2 raw = *(const uint2*)(X + (size_t)node * (CIN / 2) + c / 2);
            *(uint2*)(As + r * AP + c) = raw;
        }
    } else {
        const float* X = (const float*)Xv;
        for (int i = t * 4; i < BM * CIN; i += 256 * 4) {
            int r = i / CIN, c = i % CIN;
            int node = n0 + r; if (node > n - 1) node = n - 1;
            float4 v = *(const float4*)(X + (size_t)node * CIN + c);
            uint2 raw;
            *(__half2*)&raw.x = __floats2half2_rn(v.x, v.y);
            *(__half2*)&raw.y = __floats2half2_rn(v.z, v.w);
            *(uint2*)(As + r * AP + c) = raw;
        }
    }
    __syncthreads();

    const int w = t >> 5, lane = t & 31;
    const int wm = w / WN, wn = w % WN;

    float d[2][4][4];
#pragma unroll
    for (int mi = 0; mi < 2; mi++)
#pragma unroll
        for (int ni = 0; ni < 4; ni++)
#pragma unroll
            for (int j = 0; j < 4; j++) d[mi][ni][j] = 0.f;

    unsigned a_base = (unsigned)__cvta_generic_to_shared(
        As + (wm * 32 + (lane & 15)) * AP + (lane >> 4) * 8);
    unsigned b_base = (unsigned)__cvta_generic_to_shared(
        Bs + (lane & 15) * BP + wn * 32 + (lane >> 4) * 8);

#pragma unroll
    for (int k0 = 0; k0 < CIN; k0 += 16) {
        uint4 A0, A1, B0, B1;
        LDSM_X4(A0, a_base + k0 * 2);
        LDSM_X4(A1, a_base + k0 * 2 + 16 * AP * 2);
        LDSM_X4T(B0, b_base + k0 * BP * 2);          // n-tiles 0,1
        LDSM_X4T(B1, b_base + k0 * BP * 2 + 16 * 2); // n-tiles 2,3
        MMA16816(d[0][0], A0, B0.x, B0.y);
        MMA16816(d[0][1], A0, B0.z, B0.w);
        MMA16816(d[0][2], A0, B1.x, B1.y);
        MMA16816(d[0][3], A0, B1.z, B1.w);
        MMA16816(d[1][0], A1, B0.x, B0.y);
        MMA16816(d[1][1], A1, B0.z, B0.w);
        MMA16816(d[1][2], A1, B1.x, B1.y);
        MMA16816(d[1][3], A1, B1.z, B1.w);
    }

    // epilogue: thread owns rows (lane>>2, +8) cols (lane&3)*2..+1 per tile
    const int r0 = lane >> 2;
    const int cc = (lane & 3) * 2;
#pragma unroll
    for (int mi = 0; mi < 2; mi++) {
#pragma unroll
        for (int ni = 0; ni < 4; ni++) {
            int col = wn * 32 + ni * 8 + cc;
#pragma unroll
            for (int h = 0; h < 2; h++) {            // row halves (+0, +8)
                int node = n0 + wm * 32 + mi * 16 + h * 8 + r0;
                if (node < n) {
                    float v0 = d[mi][ni][h * 2 + 0];
                    float v1 = d[mi][ni][h * 2 + 1];
                    if (OH16) {
                        *(__half2*)(OUT16 + (size_t)node * (COUT / 2) + col / 2)
                            = __floats2half2_rn(v0, v1);
                    } else {
                        if (BIAS) {
                            float2 bv = *(const float2*)(Bb + col);
                            v0 += bv.x; v1 += bv.y;
                        }
                        float2 o = make_float2(v0, v1);
                        *(float2*)(OUT + (size_t)node * COUT + col) = o;
                    }
                }
            }
        }
    }
}

// ---------------------------------------------------------------------------
extern "C" void kernel_launch(void* const* d_in, const int* in_sizes, int n_in,
                              void* d_out, int out_size) {
    const float* x     = (const float*)d_in[0];
    const int*   ei    = (const int*)d_in[1];
    const float* W_enc = (const float*)d_in[2];
    const float* b_enc = (const float*)d_in[3];
    const float* W_dec = (const float*)d_in[4];
    const float* b_dec = (const float*)d_in[5];

    const int N = in_sizes[0] / 128;   // 100000
    const int E = in_sizes[1] / 2;     // 1600000
    const int* src = ei;
    const int* dst = ei + E;

    float* out_emb = (float*)d_out;                 // [N, 64]
    float* out_rec = out_emb + (size_t)N * 64;      // [N, 128]

    // real device addresses of scratch symbols (host shadow addr is invalid)
    __half2* hh = nullptr;          cudaGetSymbolAddress((void**)&hh, g_hh);
    __half2* eh = nullptr;          cudaGetSymbolAddress((void**)&eh, g_eh);
    int* cnt_dev = nullptr;         cudaGetSymbolAddress((void**)&cnt_dev, g_cnt);

    // dynamic smem: enc 53248 B (> 48K default), dec 26624 B
    constexpr int SMEM_ENC = (128 * (128 + 8) + 128 * (64 + 8)) * 2;   // 53248
    constexpr int SMEM_DEC = (64 * (64 + 8) + 64 * (128 + 8)) * 2;     // 26624
    cudaFuncSetAttribute(k_gemm_t<128, 64, false, false, true>,
                         cudaFuncAttributeMaxDynamicSharedMemorySize, SMEM_ENC);
    cudaFuncSetAttribute(k_gemm_t<64, 128, true, true, false>,
                         cudaFuncAttributeMaxDynamicSharedMemorySize, SMEM_DEC);

    // lazily-created side stream + fork/join events (resource init only; every
    // call enqueues identical work). Fallback: default stream (still correct).
    static cudaStream_t s2 = nullptr;
    static cudaEvent_t evFork = nullptr, evJoin = nullptr;
    static bool forkOK = false;
    static bool inited = false;
    if (!inited) {
        inited = true;
        if (cudaStreamCreateWithFlags(&s2, cudaStreamNonBlocking) == cudaSuccess &&
            cudaEventCreateWithFlags(&evFork, cudaEventDisableTiming) == cudaSuccess &&
            cudaEventCreateWithFlags(&evJoin, cudaEventDisableTiming) == cudaSuccess)
            forkOK = true;
    }

    const int TB = 256;
    const int nbE4 = ((E >> 2) + (E & 3) + TB - 1) / TB;
    cudaStream_t sb = forkOK ? s2 : (cudaStream_t)0;   // build stream

    // ---- fork: CSR build chain (independent of gemm1) ----
    if (forkOK) {
        cudaEventRecord(evFork, 0);
        cudaStreamWaitEvent(sb, evFork, 0);
    }
    cudaMemsetAsync(cnt_dev, 0, (size_t)N * sizeof(int), sb);
    k_hist<<<nbE4, TB, 0, sb>>>(dst, E);
    k_scan1<<<NB_SCAN, 1024, 0, sb>>>(N);           // also writes g_dinv
    k_scan23<<<NB_SCAN, 1024, 0, sb>>>(N);
    k_fill<<<nbE4, TB, 0, sb>>>(src, dst, E);
    if (forkOK) cudaEventRecord(evJoin, sb);

    // ---- concurrent on stream 0: gemm1 (128->64, HMMA), fp16 output ----
    k_gemm_t<128, 64, false, false, true><<<(N + 127) / 128, 256, SMEM_ENC>>>(
        x, W_enc, nullptr, nullptr, hh, N);

    // ---- join, then serial tail ----
    if (forkOK) cudaStreamWaitEvent(0, evJoin, 0);
    {
        int blocks = (N * 32 + TB - 1) / TB;   // warp per node
        // agg1: gather fp16 h (scaled by dinv[s] in-loop)
        //       -> fp32 out_emb + fp16 eh PRE-SCALED by dinv[w]
        k_agg64h<false, true, true, true, true><<<blocks, TB>>>(
            hh, out_emb, eh, b_enc, N);
        // agg2: pure-sum gather of pre-scaled eh -> fp16 hh (gemm2 input)
        k_agg64h<true, false, false, true, false><<<blocks, TB>>>(
            eh, nullptr, hh, nullptr, N);
    }
    // gemm2 (64->128, HMMA), fp32 output + bias
    k_gemm_t<64, 128, true, true, false><<<(N + 63) / 64, 256, SMEM_DEC>>>(
        hh, W_dec, b_dec, out_rec, nullptr, N);
}

// round 13
// speedup vs baseline: 1.6227x; 1.0124x over previous
#include <cuda_runtime.h>
#include <cuda_fp16.h>
#include <math.h>

// ---------------------------------------------------------------------------
// localAE: two stacked GCNConv layers.
//   loc_emb = GCN(x, W_enc, b_enc)          [N, 64]
//   loc_rec = GCN(loc_emb, W_dec, b_dec)    [N, 128]
// GCN(x) = D^-1/2 (A+I) D^-1/2 (x W) + b, deg = in-degree(dst) + 1
//
// Pipeline (linearity of aggregation used for the decoder):
//   g_hh  = fp16( x @ W_enc )              (HMMA gemm 128->64)  ── stream 0
//   CSR build (hist/scan/fill)             (independent)        ── side stream
//   emb   = agg(g_hh) + b_enc  -> fp32 out_emb
//           + fp16 g_eh PRE-SCALED by dinv[w]                    (fp16 gather)
//   g_hh  = fp16( agg_prescaled(g_eh) )                          (pure-sum gather)
//   rec   = g_hh @ W_dec + b_dec           (HMMA gemm 64->128, fp32 out)
// ---------------------------------------------------------------------------

#define NN   100000
#define EMAX 1600000
#define NB_SCAN ((NN + 1023) / 1024)   // 98

// scratch (static device globals: allocation-free)
__device__ __half2 g_hh[(size_t)NN * 32];   // fp16 features (reused both layers)
__device__ __half2 g_eh[(size_t)NN * 32];   // fp16 emb*dinv (gather source 2)
__device__ float   g_dinv[NN];
__device__ int     g_cnt[NN];               // in-degree (without self loop)
__device__ int     g_ptr[NN];               // CSR row start
__device__ int     g_cur[NN];               // fill cursor
__device__ int     g_csr[EMAX];             // src ids grouped by dst
__device__ int     g_bsum[NB_SCAN];

// ---------------------------------------------------------------------------
// histogram of dst, int4-vectorized (atomic results unused -> REDG, no
// latency dependence; issue-bound and cheap)
__global__ void k_hist(const int* __restrict__ dst, int E) {
    int i = blockIdx.x * blockDim.x + threadIdx.x;
    int E4 = E >> 2;
    if (i < E4) {
        int4 v = *(const int4*)(dst + i * 4);
        atomicAdd(&g_cnt[v.x], 1);
        atomicAdd(&g_cnt[v.y], 1);
        atomicAdd(&g_cnt[v.z], 1);
        atomicAdd(&g_cnt[v.w], 1);
    } else {
        int e = E4 * 4 + (i - E4);
        if (e < E) atomicAdd(&g_cnt[dst[e]], 1);
    }
}

// ---- scan stage 1 (shuffle-based) + dinv fused -----------------------------
__global__ void k_scan1(int n) {           // block = 1024
    int t = threadIdx.x;
    int lane = t & 31, wid = t >> 5;
    int gi = blockIdx.x * 1024 + t;
    int v = (gi < n) ? g_cnt[gi] : 0;
    if (gi < n) g_dinv[gi] = 1.0f / sqrtf((float)(v + 1));  // +1 self loop

    int x = v;
#pragma unroll
    for (int o = 1; o < 32; o <<= 1) {
        int y = __shfl_up_sync(0xffffffffu, x, o);
        if (lane >= o) x += y;
    }
    __shared__ int wsum[32];
    if (lane == 31) wsum[wid] = x;
    __syncthreads();
    if (wid == 0) {
        int s = wsum[lane];
#pragma unroll
        for (int o = 1; o < 32; o <<= 1) {
            int y = __shfl_up_sync(0xffffffffu, s, o);
            if (lane >= o) s += y;
        }
        wsum[lane] = s;
    }
    __syncthreads();
    int base = (wid > 0) ? wsum[wid - 1] : 0;
    int incl = x + base;
    if (gi < n) g_ptr[gi] = incl - v;        // exclusive
    if (t == 1023) g_bsum[blockIdx.x] = incl;
}

// ---- merged scan stages 2+3: each block sums preceding block totals --------
__global__ void k_scan23(int n) {           // block = 1024, grid = NB_SCAN
    __shared__ int boff;
    int t = threadIdx.x;
    if (t < 32) {
        int sum = 0;
        for (int i = t; i < (int)blockIdx.x; i += 32) sum += g_bsum[i];
#pragma unroll
        for (int o = 16; o; o >>= 1) sum += __shfl_down_sync(0xffffffffu, sum, o);
        if (t == 0) boff = sum;
    }
    __syncthreads();
    int gi = blockIdx.x * 1024 + t;
    if (gi < n) {
        int p = g_ptr[gi] + boff;
        g_ptr[gi] = p;
        g_cur[gi] = p;
    }
}

// CSR fill: one edge per thread (atomic WITH return -> keep max warp-level
// MLP; the int4 variant serializes 4 dependent ~318cyc round trips and is
// 3x slower — measured R12)
__global__ void k_fill(const int* __restrict__ src, const int* __restrict__ dst,
                       int E) {
    int e = blockIdx.x * blockDim.x + threadIdx.x;
    if (e < E) {
        int pos = atomicAdd(&g_cur[dst[e]], 1);
        g_csr[pos] = src[e];
    }
}

// ---------------------------------------------------------------------------
// CSR aggregation at 64 channels, fp16 gather source. One warp per node.
// Edge loop unrolled by 4 (four independent gathers in flight per half-warp).
// PRE:   features are pre-scaled by dinv[s] -> pure sum (no dinv gather).
// BIAS:  add bias (fp32 path). W32: write fp32. W16: write fp16 copy.
// W16PRE: pre-scale the fp16 copy by dinv[w] (feeds the next PRE gather).
// ---------------------------------------------------------------------------
template<bool PRE, bool BIAS, bool W32, bool W16, bool W16PRE>
__global__ void k_agg64h(const __half2* __restrict__ feat,
                         float* __restrict__ out32,
                         __half2* __restrict__ out16,
                         const float* __restrict__ B, int n) {
    int w    = (blockIdx.x * blockDim.x + threadIdx.x) >> 5;   // node
    int lane = threadIdx.x & 31;
    if (w >= n) return;
    int c4   = lane & 15;        // 4-channel group -> half2 index c4*2
    int half = lane >> 4;        // 0 or 1
    int start = g_ptr[w];
    int cnt   = g_cnt[w];

    float4 acc = make_float4(0.f, 0.f, 0.f, 0.f);
    int k = half;
    for (; k + 6 < cnt; k += 8) {          // edges k, k+2, k+4, k+6
        int s0 = g_csr[start + k];
        int s1 = g_csr[start + k + 2];
        int s2 = g_csr[start + k + 4];
        int s3 = g_csr[start + k + 6];
        uint2 r0 = *(const uint2*)(feat + (size_t)s0 * 32 + c4 * 2);
        uint2 r1 = *(const uint2*)(feat + (size_t)s1 * 32 + c4 * 2);
        uint2 r2 = *(const uint2*)(feat + (size_t)s2 * 32 + c4 * 2);
        uint2 r3 = *(const uint2*)(feat + (size_t)s3 * 32 + c4 * 2);
        float sc0 = PRE ? 1.0f : g_dinv[s0];
        float sc1 = PRE ? 1.0f : g_dinv[s1];
        float sc2 = PRE ? 1.0f : g_dinv[s2];
        float sc3 = PRE ? 1.0f : g_dinv[s3];
        float2 a0 = __half22float2(*(const __half2*)&r0.x);
        float2 b0 = __half22float2(*(const __half2*)&r0.y);
        float2 a1 = __half22float2(*(const __half2*)&r1.x);
        float2 b1 = __half22float2(*(const __half2*)&r1.y);
        float2 a2 = __half22float2(*(const __half2*)&r2.x);
        float2 b2 = __half22float2(*(const __half2*)&r2.y);
        float2 a3 = __half22float2(*(const __half2*)&r3.x);
        float2 b3 = __half22float2(*(const __half2*)&r3.y);
        if (PRE) {
            acc.x += (a0.x + a1.x) + (a2.x + a3.x);
            acc.y += (a0.y + a1.y) + (a2.y + a3.y);
            acc.z += (b0.x + b1.x) + (b2.x + b3.x);
            acc.w += (b0.y + b1.y) + (b2.y + b3.y);
        } else {
            acc.x += a0.x * sc0 + a1.x * sc1 + a2.x * sc2 + a3.x * sc3;
            acc.y += a0.y * sc0 + a1.y * sc1 + a2.y * sc2 + a3.y * sc3;
            acc.z += b0.x * sc0 + b1.x * sc1 + b2.x * sc2 + b3.x * sc3;
            acc.w += b0.y * sc0 + b1.y * sc1 + b2.y * sc2 + b3.y * sc3;
        }
    }
    for (; k < cnt; k += 2) {               // remainder edges
        int s = g_csr[start + k];
        float sc = PRE ? 1.0f : g_dinv[s];
        uint2 raw = *(const uint2*)(feat + (size_t)s * 32 + c4 * 2);
        float2 fa = __half22float2(*(const __half2*)&raw.x);
        float2 fb = __half22float2(*(const __half2*)&raw.y);
        acc.x += fa.x * sc; acc.y += fa.y * sc;
        acc.z += fb.x * sc; acc.w += fb.y * sc;
    }
    if (half == 0) {                        // self loop (PRE: already scaled)
        float sc = PRE ? 1.0f : g_dinv[w];
        uint2 raw = *(const uint2*)(feat + (size_t)w * 32 + c4 * 2);
        float2 fa = __half22float2(*(const __half2*)&raw.x);
        float2 fb = __half22float2(*(const __half2*)&raw.y);
        acc.x += fa.x * sc; acc.y += fa.y * sc;
        acc.z += fb.x * sc; acc.w += fb.y * sc;
    }
    acc.x += __shfl_down_sync(0xffffffffu, acc.x, 16);
    acc.y += __shfl_down_sync(0xffffffffu, acc.y, 16);
    acc.z += __shfl_down_sync(0xffffffffu, acc.z, 16);
    acc.w += __shfl_down_sync(0xffffffffu, acc.w, 16);

    if (half == 0) {
        float dd = g_dinv[w];
        float4 o = make_float4(acc.x * dd, acc.y * dd, acc.z * dd, acc.w * dd);
        if (BIAS) {
            float4 bv = *(const float4*)(B + c4 * 4);
            o.x += bv.x; o.y += bv.y; o.z += bv.z; o.w += bv.w;
        }
        if (W32)
            *(float4*)(out32 + (size_t)w * 64 + c4 * 4) = o;
        if (W16) {
            float s16 = W16PRE ? dd : 1.0f;
            uint2 raw;
            *(__half2*)&raw.x = __float22half2_rn(make_float2(o.x * s16, o.y * s16));
            *(__half2*)&raw.y = __float22half2_rn(make_float2(o.z * s16, o.w * s16));
            *(uint2*)(out16 + (size_t)w * 32 + c4 * 2) = raw;
        }
    }
}

// ---------------------------------------------------------------------------
// Tensor-core GEMM: OUT[n, COUT] = X[n, CIN] @ W[CIN, COUT] (+bias)
// fp16 inputs (converted in smem staging), fp32 accumulate (mma.m16n8k16).
// 8 warps; warp tile 32x32; A padded CIN+8, B padded COUT+8 (ldmatrix
// row stride ≡ 16 mod 128 bytes -> conflict-free).
// AH16: X is fp16 (half2). OH16: write fp16 to OUT16, else fp32 (+bias).
// ---------------------------------------------------------------------------
#define LDSM_X4(f, addr) \
    asm volatile("ldmatrix.sync.aligned.m8n8.x4.shared.b16 {%0,%1,%2,%3}, [%4];" \
        : "=r"(f.x), "=r"(f.y), "=r"(f.z), "=r"(f.w) : "r"(addr))
#define LDSM_X4T(f, addr) \
    asm volatile("ldmatrix.sync.aligned.m8n8.x4.trans.shared.b16 {%0,%1,%2,%3}, [%4];" \
        : "=r"(f.x), "=r"(f.y), "=r"(f.z), "=r"(f.w) : "r"(addr))
#define MMA16816(d, a, b0, b1) \
    asm volatile("mma.sync.aligned.m16n8k16.row.col.f32.f16.f16.f32 " \
        "{%0,%1,%2,%3}, {%4,%5,%6,%7}, {%8,%9}, {%0,%1,%2,%3};" \
        : "+f"(d[0]), "+f"(d[1]), "+f"(d[2]), "+f"(d[3]) \
        : "r"(a.x), "r"(a.y), "r"(a.z), "r"(a.w), "r"(b0), "r"(b1))

template<int CIN, int COUT, bool BIAS, bool AH16, bool OH16>
__global__ void __launch_bounds__(256)
k_gemm_t(const void* __restrict__ Xv, const float* __restrict__ W,
         const float* __restrict__ Bb, float* __restrict__ OUT,
         __half2* __restrict__ OUT16, int n) {
    constexpr int WN = COUT / 32;      // 2 (enc) / 4 (dec)
    constexpr int WM = 8 / WN;         // 4 / 2
    constexpr int BM = WM * 32;        // 128 / 64
    constexpr int AP = CIN + 8;        // padded A row (halves)
    constexpr int BP = COUT + 8;       // padded B row (halves)
    extern __shared__ __half smh[];
    __half* As = smh;                  // BM * AP
    __half* Bs = smh + BM * AP;        // CIN * BP

    const int t  = threadIdx.x;
    const int n0 = blockIdx.x * BM;

    // stage W -> fp16 smem
    for (int i = t * 4; i < CIN * COUT; i += 256 * 4) {
        int r = i / COUT, c = i % COUT;
        float4 v = *(const float4*)(W + i);
        uint2 raw;
        *(__half2*)&raw.x = __floats2half2_rn(v.x, v.y);
        *(__half2*)&raw.y = __floats2half2_rn(v.z, v.w);
        *(uint2*)(Bs + r * BP + c) = raw;
    }
    // stage A -> fp16 smem (tail rows clamped, stores guarded in epilogue)
    if (AH16) {
        const __half2* X = (const __half2*)Xv;
        for (int i = t * 4; i < BM * CIN; i += 256 * 4) {
            int r = i / CIN, c = i % CIN;
            int node = n0 + r; if (node > n - 1) node = n - 1;
            uint2 raw = *(const uint2*)(X + (size_t)node * (CIN / 2) + c / 2);
            *(uint2*)(As + r * AP + c) = raw;
        }
    } else {
        const float* X = (const float*)Xv;
        for (int i = t * 4; i < BM * CIN; i += 256 * 4) {
            int r = i / CIN, c = i % CIN;
            int node = n0 + r; if (node > n - 1) node = n - 1;
            float4 v = *(const float4*)(X + (size_t)node * CIN + c);
            uint2 raw;
            *(__half2*)&raw.x = __floats2half2_rn(v.x, v.y);
            *(__half2*)&raw.y = __floats2half2_rn(v.z, v.w);
            *(uint2*)(As + r * AP + c) = raw;
        }
    }
    __syncthreads();

    const int w = t >> 5, lane = t & 31;
    const int wm = w / WN, wn = w % WN;

    float d[2][4][4];
#pragma unroll
    for (int mi = 0; mi < 2; mi++)
#pragma unroll
        for (int ni = 0; ni < 4; ni++)
#pragma unroll
            for (int j = 0; j < 4; j++) d[mi][ni][j] = 0.f;

    unsigned a_base = (unsigned)__cvta_generic_to_shared(
        As + (wm * 32 + (lane & 15)) * AP + (lane >> 4) * 8);
    unsigned b_base = (unsigned)__cvta_generic_to_shared(
        Bs + (lane & 15) * BP + wn * 32 + (lane >> 4) * 8);

#pragma unroll
    for (int k0 = 0; k0 < CIN; k0 += 16) {
        uint4 A0, A1, B0, B1;
        LDSM_X4(A0, a_base + k0 * 2);
        LDSM_X4(A1, a_base + k0 * 2 + 16 * AP * 2);
        LDSM_X4T(B0, b_base + k0 * BP * 2);          // n-tiles 0,1
        LDSM_X4T(B1, b_base + k0 * BP * 2 + 16 * 2); // n-tiles 2,3
        MMA16816(d[0][0], A0, B0.x, B0.y);
        MMA16816(d[0][1], A0, B0.z, B0.w);
        MMA16816(d[0][2], A0, B1.x, B1.y);
        MMA16816(d[0][3], A0, B1.z, B1.w);
        MMA16816(d[1][0], A1, B0.x, B0.y);
        MMA16816(d[1][1], A1, B0.z, B0.w);
        MMA16816(d[1][2], A1, B1.x, B1.y);
        MMA16816(d[1][3], A1, B1.z, B1.w);
    }

    // epilogue: thread owns rows (lane>>2, +8) cols (lane&3)*2..+1 per tile
    const int r0 = lane >> 2;
    const int cc = (lane & 3) * 2;
#pragma unroll
    for (int mi = 0; mi < 2; mi++) {
#pragma unroll
        for (int ni = 0; ni < 4; ni++) {
            int col = wn * 32 + ni * 8 + cc;
#pragma unroll
            for (int h = 0; h < 2; h++) {            // row halves (+0, +8)
                int node = n0 + wm * 32 + mi * 16 + h * 8 + r0;
                if (node < n) {
                    float v0 = d[mi][ni][h * 2 + 0];
                    float v1 = d[mi][ni][h * 2 + 1];
                    if (OH16) {
                        *(__half2*)(OUT16 + (size_t)node * (COUT / 2) + col / 2)
                            = __floats2half2_rn(v0, v1);
                    } else {
                        if (BIAS) {
                            float2 bv = *(const float2*)(Bb + col);
                            v0 += bv.x; v1 += bv.y;
                        }
                        float2 o = make_float2(v0, v1);
                        *(float2*)(OUT + (size_t)node * COUT + col) = o;
                    }
                }
            }
        }
    }
}

// ---------------------------------------------------------------------------
extern "C" void kernel_launch(void* const* d_in, const int* in_sizes, int n_in,
                              void* d_out, int out_size) {
    const float* x     = (const float*)d_in[0];
    const int*   ei    = (const int*)d_in[1];
    const float* W_enc = (const float*)d_in[2];
    const float* b_enc = (const float*)d_in[3];
    const float* W_dec = (const float*)d_in[4];
    const float* b_dec = (const float*)d_in[5];

    const int N = in_sizes[0] / 128;   // 100000
    const int E = in_sizes[1] / 2;     // 1600000
    const int* src = ei;
    const int* dst = ei + E;

    float* out_emb = (float*)d_out;                 // [N, 64]
    float* out_rec = out_emb + (size_t)N * 64;      // [N, 128]

    // real device addresses of scratch symbols (host shadow addr is invalid)
    __half2* hh = nullptr;          cudaGetSymbolAddress((void**)&hh, g_hh);
    __half2* eh = nullptr;          cudaGetSymbolAddress((void**)&eh, g_eh);
    int* cnt_dev = nullptr;         cudaGetSymbolAddress((void**)&cnt_dev, g_cnt);

    // dynamic smem: enc 53248 B (> 48K default), dec 26624 B
    constexpr int SMEM_ENC = (128 * (128 + 8) + 128 * (64 + 8)) * 2;   // 53248
    constexpr int SMEM_DEC = (64 * (64 + 8) + 64 * (128 + 8)) * 2;     // 26624
    cudaFuncSetAttribute(k_gemm_t<128, 64, false, false, true>,
                         cudaFuncAttributeMaxDynamicSharedMemorySize, SMEM_ENC);
    cudaFuncSetAttribute(k_gemm_t<64, 128, true, true, false>,
                         cudaFuncAttributeMaxDynamicSharedMemorySize, SMEM_DEC);

    // lazily-created side stream + fork/join events (resource init only; every
    // call enqueues identical work). Fallback: default stream (still correct).
    static cudaStream_t s2 = nullptr;
    static cudaEvent_t evFork = nullptr, evJoin = nullptr;
    static bool forkOK = false;
    static bool inited = false;
    if (!inited) {
        inited = true;
        if (cudaStreamCreateWithFlags(&s2, cudaStreamNonBlocking) == cudaSuccess &&
            cudaEventCreateWithFlags(&evFork, cudaEventDisableTiming) == cudaSuccess &&
            cudaEventCreateWithFlags(&evJoin, cudaEventDisableTiming) == cudaSuccess)
            forkOK = true;
    }

    const int TB = 256;
    const int nbE  = (E + TB - 1) / TB;
    const int nbE4 = ((E >> 2) + (E & 3) + TB - 1) / TB;
    cudaStream_t sb = forkOK ? s2 : (cudaStream_t)0;   // build stream

    // ---- fork: CSR build chain (independent of gemm1) ----
    if (forkOK) {
        cudaEventRecord(evFork, 0);
        cudaStreamWaitEvent(sb, evFork, 0);
    }
    cudaMemsetAsync(cnt_dev, 0, (size_t)N * sizeof(int), sb);
    k_hist<<<nbE4, TB, 0, sb>>>(dst, E);
    k_scan1<<<NB_SCAN, 1024, 0, sb>>>(N);           // also writes g_dinv
    k_scan23<<<NB_SCAN, 1024, 0, sb>>>(N);
    k_fill<<<nbE, TB, 0, sb>>>(src, dst, E);
    if (forkOK) cudaEventRecord(evJoin, sb);

    // ---- concurrent on stream 0: gemm1 (128->64, HMMA), fp16 output ----
    k_gemm_t<128, 64, false, false, true><<<(N + 127) / 128, 256, SMEM_ENC>>>(
        x, W_enc, nullptr, nullptr, hh, N);

    // ---- join, then serial tail ----
    if (forkOK) cudaStreamWaitEvent(0, evJoin, 0);
    {
        int blocks = (N * 32 + TB - 1) / TB;   // warp per node
        // agg1: gather fp16 h (scaled by dinv[s] in-loop)
        //       -> fp32 out_emb + fp16 eh PRE-SCALED by dinv[w]
        k_agg64h<false, true, true, true, true><<<blocks, TB>>>(
            hh, out_emb, eh, b_enc, N);
        // agg2: pure-sum gather of pre-scaled eh -> fp16 hh (gemm2 input)
        k_agg64h<true, false, false, true, false><<<blocks, TB>>>(
            eh, nullptr, hh, nullptr, N);
    }
    // gemm2 (64->128, HMMA), fp32 output + bias
    k_gemm_t<64, 128, true, true, false><<<(N + 63) / 64, 256, SMEM_DEC>>>(
        hh, W_dec, b_dec, out_rec, nullptr, N);
}